// round 6
// baseline (speedup 1.0000x reference)
#include <cuda_runtime.h>
#include <math.h>

// ---------------- problem constants ----------------
#define B_   2
#define T_   1024
#define NT_  30
#define H_   1024
#define L_   8
#define F_   2816
#define NH_  16
#define HD_  64
#define R_   16
#define M_   (B_*T_)                 // 2048 tokens
#define MH_  ((size_t)M_*H_)
#define HH_  ((size_t)H_*H_)
#define HF_  ((size_t)H_*F_)
#define MF_  ((size_t)M_*F_)

// ---------------- scratch (device globals: no allocation allowed) ----------------
__device__ float g_h  [M_*H_];
__device__ float g_hn [M_*H_];
__device__ float g_qkv[3*M_*H_];
__device__ float g_att[M_*H_];
__device__ float g_gu [2*M_*F_];
__device__ float g_act[M_*F_];
// fused (W + 2 * A^T B^T) effective weights
__device__ float g_Wq [L_*3*H_*H_];
__device__ float g_Wo_[L_*H_*H_];
__device__ float g_Wgu[L_*2*H_*F_];
__device__ float g_Wd_[L_*F_*H_];

// ---------------- LoRA fold: Weff[i][j] = W[i][j] + 2 * sum_r A[r][i]*B[j][r] ----------------
__global__ void fuse_lora_kernel(const float* __restrict__ W, const float* __restrict__ A,
                                 const float* __restrict__ Bm, float* __restrict__ Weff,
                                 int KK, int N) {
    const int mat = blockIdx.z;
    const int i   = blockIdx.y;                       // row in [KK]
    const int j   = blockIdx.x*256 + threadIdx.x;     // col in [N]
    const float* Wm  = W  + (size_t)mat*KK*N;
    const float* Am  = A  + (size_t)mat*R_*KK;
    const float* Bmm = Bm + (size_t)mat*N*R_;
    __shared__ float As[R_];
    if (threadIdx.x < R_) As[threadIdx.x] = Am[(size_t)threadIdx.x*KK + i];
    __syncthreads();
    if (j < N) {
        float s = 0.f;
        #pragma unroll
        for (int r = 0; r < R_; r++) s += As[r] * Bmm[(size_t)j*R_ + r];
        Weff[(size_t)mat*KK*N + (size_t)i*N + j] = Wm[(size_t)i*N + j] + 2.0f * s;
    }
}

// ---------------- h = x @ state_W + state_b ----------------
__global__ void init_h_kernel(const float* __restrict__ x, const float* __restrict__ W,
                              const float* __restrict__ b) {
    const int m = blockIdx.y;
    const int j = blockIdx.x*256 + threadIdx.x;
    __shared__ float xs[NT_];
    if (threadIdx.x < NT_) xs[threadIdx.x] = x[(size_t)m*NT_ + threadIdx.x];
    __syncthreads();
    float s = b[j];
    #pragma unroll
    for (int k = 0; k < NT_; k++) s += xs[k]*W[(size_t)k*H_ + j];
    g_h[(size_t)m*H_ + j] = s;
}

// ---------------- RMSNorm ----------------
__global__ void rms_kernel(const float* __restrict__ in, const float* __restrict__ w,
                           float* __restrict__ out) {
    const int m = blockIdx.x;
    const float* row = in + (size_t)m*H_;
    float s = 0.f;
    for (int i = threadIdx.x; i < H_; i += 256) { float v = row[i]; s += v*v; }
    __shared__ float red[8];
    #pragma unroll
    for (int o = 16; o; o >>= 1) s += __shfl_xor_sync(0xffffffffu, s, o);
    if ((threadIdx.x & 31) == 0) red[threadIdx.x >> 5] = s;
    __syncthreads();
    if (threadIdx.x < 8) {
        float v = red[threadIdx.x];
        #pragma unroll
        for (int o = 4; o; o >>= 1) v += __shfl_xor_sync(0xffu, v, o);
        if (threadIdx.x == 0) red[0] = v;
    }
    __syncthreads();
    const float inv = rsqrtf(red[0]*(1.0f/H_) + 1e-6f);
    for (int i = threadIdx.x; i < H_; i += 256) out[(size_t)m*H_ + i] = row[i]*inv*w[i];
}

// ---------------- RoPE (in place, q & k via blockIdx.y) ----------------
__global__ void rope_kernel(float* __restrict__ qkv) {
    const int idx = blockIdx.x*256 + threadIdx.x;          // over M_*NH_*32
    if (idx >= M_*NH_*32) return;
    const int i  = idx & 31;
    const int nh = (idx >> 5) & 15;
    const int m  = idx >> 9;
    const int t  = m & (T_-1);
    float* base = qkv + (size_t)blockIdx.y*MH_ + (size_t)m*H_ + nh*HD_;
    const float x1 = base[i], x2 = base[i+32];
    const float inv = expf(-(float)i * (1.0f/32.0f) * 9.210340371976184f); // ln(10000)
    const float ang = (float)t * inv;
    const float c = cosf(ang), s = sinf(ang);
    base[i]    = x1*c - x2*s;
    base[i+32] = x2*c + x1*s;
}

// ---------------- flash attention (fp32, causal) ----------------
#define AQ 64
#define AK 32
__global__ void attn_kernel(const float* __restrict__ qkv, float* __restrict__ att) {
    const int qt = blockIdx.x, nh = blockIdx.y, b = blockIdx.z;
    const int tid = threadIdx.x;
    const int tx = tid & 15;        // 2 S-cols / 4 O-cols
    const int ty = tid >> 4;        // 4 rows
    __shared__ __align__(16) float Qs[AQ][HD_+4];
    __shared__ __align__(16) float Ks[AK][HD_+4];
    __shared__ __align__(16) float Vs[AK][HD_+4];
    __shared__ __align__(16) float Ps[AQ][AK+4];
    const size_t baseQ  = (size_t)(b*T_ + qt*AQ)*H_ + nh*HD_;
    const size_t baseKV = (size_t)(b*T_)*H_ + nh*HD_;
    const float* Qg = qkv + baseQ;
    const float* Kg = qkv + MH_   + baseKV;
    const float* Vg = qkv + 2*MH_ + baseKV;
    #pragma unroll
    for (int u = 0; u < 4; u++) {
        int q = tid + u*256;
        int r = q >> 4, c = (q & 15) << 2;
        *(float4*)(&Qs[r][c]) = *(const float4*)(Qg + (size_t)r*H_ + c);
    }
    float m_i[4], l_i[4], O[4][4];
    #pragma unroll
    for (int i = 0; i < 4; i++) {
        m_i[i] = -1e30f; l_i[i] = 0.f;
        #pragma unroll
        for (int j = 0; j < 4; j++) O[i][j] = 0.f;
    }
    const int nkv = 2*qt + 2;       // causal: only tiles with k <= q_max
    for (int kvt = 0; kvt < nkv; kvt++) {
        __syncthreads();
        #pragma unroll
        for (int u = 0; u < 2; u++) {
            int q = tid + u*256;
            int r = q >> 4, c = (q & 15) << 2;
            *(float4*)(&Ks[r][c]) = *(const float4*)(Kg + (size_t)(kvt*AK + r)*H_ + c);
            *(float4*)(&Vs[r][c]) = *(const float4*)(Vg + (size_t)(kvt*AK + r)*H_ + c);
        }
        __syncthreads();
        float s[4][2] = {};
        #pragma unroll
        for (int k4 = 0; k4 < HD_; k4 += 4) {
            float4 q0 = *(const float4*)&Qs[ty*4+0][k4];
            float4 q1 = *(const float4*)&Qs[ty*4+1][k4];
            float4 q2 = *(const float4*)&Qs[ty*4+2][k4];
            float4 q3 = *(const float4*)&Qs[ty*4+3][k4];
            float4 ka = *(const float4*)&Ks[tx*2+0][k4];
            float4 kb = *(const float4*)&Ks[tx*2+1][k4];
            s[0][0] += q0.x*ka.x + q0.y*ka.y + q0.z*ka.z + q0.w*ka.w;
            s[0][1] += q0.x*kb.x + q0.y*kb.y + q0.z*kb.z + q0.w*kb.w;
            s[1][0] += q1.x*ka.x + q1.y*ka.y + q1.z*ka.z + q1.w*ka.w;
            s[1][1] += q1.x*kb.x + q1.y*kb.y + q1.z*kb.z + q1.w*kb.w;
            s[2][0] += q2.x*ka.x + q2.y*ka.y + q2.z*ka.z + q2.w*ka.w;
            s[2][1] += q2.x*kb.x + q2.y*kb.y + q2.z*kb.z + q2.w*kb.w;
            s[3][0] += q3.x*ka.x + q3.y*ka.y + q3.z*ka.z + q3.w*ka.w;
            s[3][1] += q3.x*kb.x + q3.y*kb.y + q3.z*kb.z + q3.w*kb.w;
        }
        #pragma unroll
        for (int i = 0; i < 4; i++) {
            const int qrow = qt*AQ + ty*4 + i;
            #pragma unroll
            for (int j = 0; j < 2; j++) {
                const int kcol = kvt*AK + tx*2 + j;
                s[i][j] = (kcol <= qrow) ? s[i][j]*0.125f : -1e9f;
            }
        }
        #pragma unroll
        for (int i = 0; i < 4; i++) {
            float mx = fmaxf(s[i][0], s[i][1]);
            #pragma unroll
            for (int o = 8; o; o >>= 1) mx = fmaxf(mx, __shfl_xor_sync(0xffffffffu, mx, o));
            const float mn = fmaxf(m_i[i], mx);
            const float p0 = expf(s[i][0]-mn), p1 = expf(s[i][1]-mn);
            float rs = p0 + p1;
            #pragma unroll
            for (int o = 8; o; o >>= 1) rs += __shfl_xor_sync(0xffffffffu, rs, o);
            const float alpha = expf(m_i[i]-mn);
            m_i[i] = mn;
            l_i[i] = l_i[i]*alpha + rs;
            #pragma unroll
            for (int j = 0; j < 4; j++) O[i][j] *= alpha;
            Ps[ty*4+i][tx*2+0] = p0;
            Ps[ty*4+i][tx*2+1] = p1;
        }
        __syncthreads();
        #pragma unroll
        for (int k4 = 0; k4 < AK; k4 += 4) {
            float4 v0 = *(const float4*)&Vs[k4+0][tx*4];
            float4 v1 = *(const float4*)&Vs[k4+1][tx*4];
            float4 v2 = *(const float4*)&Vs[k4+2][tx*4];
            float4 v3 = *(const float4*)&Vs[k4+3][tx*4];
            #pragma unroll
            for (int i = 0; i < 4; i++) {
                float4 p = *(const float4*)&Ps[ty*4+i][k4];
                O[i][0] += p.x*v0.x + p.y*v1.x + p.z*v2.x + p.w*v3.x;
                O[i][1] += p.x*v0.y + p.y*v1.y + p.z*v2.y + p.w*v3.y;
                O[i][2] += p.x*v0.z + p.y*v1.z + p.z*v2.z + p.w*v3.z;
                O[i][3] += p.x*v0.w + p.y*v1.w + p.z*v2.w + p.w*v3.w;
            }
        }
    }
    #pragma unroll
    for (int i = 0; i < 4; i++) {
        const float invl = 1.0f/l_i[i];
        const size_t off = (size_t)(b*T_ + qt*AQ + ty*4 + i)*H_ + nh*HD_ + tx*4;
        float4 v = make_float4(O[i][0]*invl, O[i][1]*invl, O[i][2]*invl, O[i][3]*invl);
        *(float4*)(att + off) = v;
    }
}

// ---------------- tiled SGEMM: C[M,N] (+)= A[M,K] @ B[K,N], batched via blockIdx.z ----------------
#define BM 128
#define BN 128
#define BK 16
template<bool ADD>
__global__ void __launch_bounds__(256, 2)
sgemm_kernel(const float* __restrict__ A, const float* __restrict__ B,
             float* __restrict__ C, int M, int N, int K,
             size_t strideB, size_t strideC) {
    B += (size_t)blockIdx.z * strideB;
    C += (size_t)blockIdx.z * strideC;
    __shared__ __align__(16) float As[BK][BM+4];  // stride 132 (transposed A tile)
    __shared__ __align__(16) float Bs[BK][BN];
    const int tid = threadIdx.x;
    const int tx = tid & 15;
    const int ty = tid >> 4;
    const int row0 = blockIdx.y*BM;
    const int col0 = blockIdx.x*BN;
    float acc[8][8];
    #pragma unroll
    for (int i = 0; i < 8; i++)
        #pragma unroll
        for (int j = 0; j < 8; j++) acc[i][j] = 0.f;
    const float* Ap = A + (size_t)row0*K;
    const float* Bp = B + col0;
    for (int k0 = 0; k0 < K; k0 += BK) {
        #pragma unroll
        for (int u = 0; u < 2; u++) {
            int q = tid + u*256;
            int ar = q >> 2;
            int ac = (q & 3) << 2;
            float4 v = *(const float4*)(Ap + (size_t)ar*K + k0 + ac);
            As[ac+0][ar] = v.x; As[ac+1][ar] = v.y; As[ac+2][ar] = v.z; As[ac+3][ar] = v.w;
        }
        #pragma unroll
        for (int u = 0; u < 2; u++) {
            int q = tid + u*256;
            int br = q >> 5;
            int bc = (q & 31) << 2;
            *(float4*)(&Bs[br][bc]) = *(const float4*)(Bp + (size_t)(k0+br)*N + bc);
        }
        __syncthreads();
        #pragma unroll
        for (int kk = 0; kk < BK; kk++) {
            float4 a0 = *(const float4*)&As[kk][ty*4];
            float4 a1 = *(const float4*)&As[kk][64 + ty*4];
            float4 b0 = *(const float4*)&Bs[kk][tx*4];
            float4 b1 = *(const float4*)&Bs[kk][64 + tx*4];
            float a[8] = {a0.x,a0.y,a0.z,a0.w,a1.x,a1.y,a1.z,a1.w};
            float bb[8] = {b0.x,b0.y,b0.z,b0.w,b1.x,b1.y,b1.z,b1.w};
            #pragma unroll
            for (int i = 0; i < 8; i++)
                #pragma unroll
                for (int j = 0; j < 8; j++) acc[i][j] += a[i]*bb[j];
        }
        __syncthreads();
    }
    #pragma unroll
    for (int i = 0; i < 8; i++) {
        const int r = row0 + ((i < 4) ? (ty*4 + i) : (64 + ty*4 + i - 4));
        float* crow = C + (size_t)r*N + col0;
        #pragma unroll
        for (int jh = 0; jh < 2; jh++) {
            const int c = jh ? (64 + tx*4) : (tx*4);
            float4 v = make_float4(acc[i][jh*4+0], acc[i][jh*4+1], acc[i][jh*4+2], acc[i][jh*4+3]);
            if (ADD) {
                float4 o = *(const float4*)(crow + c);
                v.x += o.x; v.y += o.y; v.z += o.z; v.w += o.w;
            }
            *(float4*)(crow + c) = v;
        }
    }
}

// ---------------- SwiGLU: act = silu(g) * u ----------------
__global__ void silu_kernel(const float* __restrict__ g, const float* __restrict__ u,
                            float* __restrict__ act, int n) {
    const int i = blockIdx.x*256 + threadIdx.x;
    if (i < n) {
        const float gv = g[i];
        act[i] = (gv / (1.0f + expf(-gv))) * u[i];
    }
}

// ---------------- head: logits = latent@W + b, clamp, softmax ----------------
__global__ void head_kernel(const float* __restrict__ latent, const float* __restrict__ W,
                            const float* __restrict__ bias, const float* __restrict__ temp,
                            float* __restrict__ out) {
    const int m = blockIdx.x;
    __shared__ float xs[H_];
    __shared__ float red[8][32];
    const float* row = latent + (size_t)m*H_;
    for (int i = threadIdx.x; i < H_; i += 256) xs[i] = row[i];
    __syncthreads();
    const int n  = threadIdx.x & 31;
    const int ch = threadIdx.x >> 5;
    float p = 0.f;
    if (n < 31) {
        const int k0 = ch*128;
        for (int k = k0; k < k0 + 128; k++) p += xs[k]*W[(size_t)k*31 + n];
    }
    red[ch][n] = p;
    __syncthreads();
    if (threadIdx.x < 32) {
        float v = 0.f;
        if (n < 31) {
            #pragma unroll
            for (int c = 0; c < 8; c++) v += red[c][n];
            v += bias[n];
            v = fminf(fmaxf(v, -10.0f), 10.0f);
            out[(size_t)M_*31 + (size_t)m*31 + n] = v;     // logits_clamped (2nd output)
        }
        const float t = *temp;
        float mx = (n < 31) ? v : -1e30f;
        #pragma unroll
        for (int o = 16; o; o >>= 1) mx = fmaxf(mx, __shfl_xor_sync(0xffffffffu, mx, o));
        const float ev = (n < 31) ? expf((v - mx)/t) : 0.f;
        float sm = ev;
        #pragma unroll
        for (int o = 16; o; o >>= 1) sm += __shfl_xor_sync(0xffffffffu, sm, o);
        if (n < 31) out[(size_t)m*31 + n] = ev/sm;         // portfolio_weights (1st output)
    }
}

// ---------------- launcher ----------------
extern "C" void kernel_launch(void* const* d_in, const int* in_sizes, int n_in,
                              void* d_out, int out_size) {
    (void)in_sizes; (void)n_in; (void)out_size;
    const float* x       = (const float*)d_in[0];
    const float* temp    = (const float*)d_in[1];
    const float* state_W = (const float*)d_in[2];
    const float* state_b = (const float*)d_in[3];
    const float* ln1     = (const float*)d_in[4];
    const float* ln2     = (const float*)d_in[5];
    const float* Wqkv    = (const float*)d_in[6];
    const float* Aqkv    = (const float*)d_in[7];
    const float* Bqkv    = (const float*)d_in[8];
    const float* Wo      = (const float*)d_in[9];
    const float* Ao      = (const float*)d_in[10];
    const float* Bo      = (const float*)d_in[11];
    const float* Wgu     = (const float*)d_in[12];
    const float* Agu     = (const float*)d_in[13];
    const float* Bgu     = (const float*)d_in[14];
    const float* Wd      = (const float*)d_in[15];
    const float* Ad      = (const float*)d_in[16];
    const float* Bd      = (const float*)d_in[17];
    const float* ln_f    = (const float*)d_in[18];
    const float* head_W  = (const float*)d_in[19];
    const float* head_b  = (const float*)d_in[20];
    float* out = (float*)d_out;

    float *p_h, *p_hn, *p_qkv, *p_att, *p_gu, *p_act, *pWq, *pWo, *pWgu, *pWd;
    cudaGetSymbolAddress((void**)&p_h,   g_h);
    cudaGetSymbolAddress((void**)&p_hn,  g_hn);
    cudaGetSymbolAddress((void**)&p_qkv, g_qkv);
    cudaGetSymbolAddress((void**)&p_att, g_att);
    cudaGetSymbolAddress((void**)&p_gu,  g_gu);
    cudaGetSymbolAddress((void**)&p_act, g_act);
    cudaGetSymbolAddress((void**)&pWq,   g_Wq);
    cudaGetSymbolAddress((void**)&pWo,   g_Wo_);
    cudaGetSymbolAddress((void**)&pWgu,  g_Wgu);
    cudaGetSymbolAddress((void**)&pWd,   g_Wd_);

    // ---- fold LoRA into effective weights ----
    fuse_lora_kernel<<<dim3(4, 1024, 24), 256>>>(Wqkv, Aqkv, Bqkv, pWq, H_, H_);
    fuse_lora_kernel<<<dim3(4, 1024,  8), 256>>>(Wo,   Ao,   Bo,   pWo, H_, H_);
    fuse_lora_kernel<<<dim3(11,1024, 16), 256>>>(Wgu,  Agu,  Bgu,  pWgu, H_, F_);
    fuse_lora_kernel<<<dim3(4, 2816,  8), 256>>>(Wd,   Ad,   Bd,   pWd, F_, H_);

    // ---- embed ----
    init_h_kernel<<<dim3(4, M_), 256>>>(x, state_W, state_b);

    // ---- layers ----
    for (int l = 0; l < L_; l++) {
        rms_kernel<<<M_, 256>>>(p_h, ln1 + (size_t)l*H_, p_hn);
        sgemm_kernel<false><<<dim3(8, 16, 3), 256>>>(p_hn, pWq + (size_t)l*3*HH_, p_qkv,
                                                     M_, H_, H_, HH_, MH_);
        rope_kernel<<<dim3(4096, 2), 256>>>(p_qkv);
        attn_kernel<<<dim3(16, 16, 2), 256>>>(p_qkv, p_att);
        sgemm_kernel<true><<<dim3(8, 16, 1), 256>>>(p_att, pWo + (size_t)l*HH_, p_h,
                                                    M_, H_, H_, 0, 0);
        rms_kernel<<<M_, 256>>>(p_h, ln2 + (size_t)l*H_, p_hn);
        sgemm_kernel<false><<<dim3(22, 16, 2), 256>>>(p_hn, pWgu + (size_t)l*2*HF_, p_gu,
                                                      M_, F_, H_, HF_, MF_);
        silu_kernel<<<(int)((MF_ + 255)/256), 256>>>(p_gu, p_gu + MF_, p_act, (int)MF_);
        sgemm_kernel<true><<<dim3(8, 16, 1), 256>>>(p_act, pWd + (size_t)l*HF_, p_h,
                                                    M_, H_, F_, 0, 0);
    }

    // ---- final norm + head + softmax ----
    rms_kernel<<<M_, 256>>>(p_h, ln_f, p_hn);
    head_kernel<<<M_, 256>>>(p_hn, head_W, head_b, temp, out);
}

// round 7
// speedup vs baseline: 1.3202x; 1.3202x over previous
#include <cuda_runtime.h>
#include <math.h>
#include <stdint.h>

// ---------------- problem constants ----------------
#define B_   2
#define T_   1024
#define NT_  30
#define H_   1024
#define L_   8
#define F_   2816
#define NH_  16
#define HD_  64
#define R_   16
#define M_   (B_*T_)                 // 2048 tokens
#define MH_  ((size_t)M_*H_)
#define HH_  ((size_t)H_*H_)
#define HF_  ((size_t)H_*F_)
#define MF_  ((size_t)M_*F_)

// ---------------- scratch (device globals: no allocation allowed) ----------------
__device__ float g_h  [M_*H_];
__device__ float g_hn [M_*H_];
__device__ float g_qkv[3*M_*H_];
__device__ float g_att[M_*H_];
__device__ float g_gu [2*M_*F_];
__device__ float g_act[M_*F_];
// fused (W + 2 * A^T B^T) effective weights
__device__ float g_Wq [L_*3*H_*H_];
__device__ float g_Wo_[L_*H_*H_];
__device__ float g_Wgu[L_*2*H_*F_];
__device__ float g_Wd_[L_*F_*H_];

// ---------------- LoRA fold v2: Weff[i][j] = W[i][j] + 2 * sum_r A[r][i]*B[j][r] ----------------
// Tile: 32 rows (i) x 256 cols (j). A tile staged in smem (broadcast reads),
// B row (16 floats) held per-thread in registers. W read / Weff write coalesced.
__global__ void fuse_lora2_kernel(const float* __restrict__ W, const float* __restrict__ A,
                                  const float* __restrict__ Bm, float* __restrict__ Weff,
                                  int KK, int N) {
    const int mat = blockIdx.z;
    const int i0  = blockIdx.y * 32;
    const int j   = blockIdx.x * 256 + threadIdx.x;
    const float* Wm  = W  + (size_t)mat*KK*N;
    const float* Am  = A  + (size_t)mat*R_*KK;
    const float* Bmm = Bm + (size_t)mat*N*R_;
    float*       Om  = Weff + (size_t)mat*KK*N;

    __shared__ float As2[R_][33];
    #pragma unroll
    for (int u = 0; u < 2; u++) {
        int idx = threadIdx.x + u*256;       // 512 = 16*32
        int r = idx >> 5, ii = idx & 31;
        As2[r][ii] = Am[(size_t)r*KK + i0 + ii];
    }
    // B row in registers (float4 x4, 64B per thread, full-sector reads)
    float Bv[R_];
    {
        const float4* bp = (const float4*)(Bmm + (size_t)j*R_);
        float4 b0 = bp[0], b1 = bp[1], b2 = bp[2], b3 = bp[3];
        Bv[0]=b0.x; Bv[1]=b0.y; Bv[2]=b0.z; Bv[3]=b0.w;
        Bv[4]=b1.x; Bv[5]=b1.y; Bv[6]=b1.z; Bv[7]=b1.w;
        Bv[8]=b2.x; Bv[9]=b2.y; Bv[10]=b2.z; Bv[11]=b2.w;
        Bv[12]=b3.x; Bv[13]=b3.y; Bv[14]=b3.z; Bv[15]=b3.w;
    }
    __syncthreads();
    #pragma unroll 4
    for (int ii = 0; ii < 32; ii++) {
        float s = 0.f;
        #pragma unroll
        for (int r = 0; r < R_; r++) s += As2[r][ii] * Bv[r];
        const size_t off = (size_t)(i0 + ii)*N + j;
        Om[off] = Wm[off] + 2.0f * s;
    }
}

// ---------------- h = x @ state_W + state_b ----------------
__global__ void init_h_kernel(const float* __restrict__ x, const float* __restrict__ W,
                              const float* __restrict__ b) {
    const int m = blockIdx.y;
    const int j = blockIdx.x*256 + threadIdx.x;
    __shared__ float xs[NT_];
    if (threadIdx.x < NT_) xs[threadIdx.x] = x[(size_t)m*NT_ + threadIdx.x];
    __syncthreads();
    float s = b[j];
    #pragma unroll
    for (int k = 0; k < NT_; k++) s += xs[k]*W[(size_t)k*H_ + j];
    g_h[(size_t)m*H_ + j] = s;
}

// ---------------- RMSNorm ----------------
__global__ void rms_kernel(const float* __restrict__ in, const float* __restrict__ w,
                           float* __restrict__ out) {
    const int m = blockIdx.x;
    const float* row = in + (size_t)m*H_;
    float s = 0.f;
    for (int i = threadIdx.x; i < H_; i += 256) { float v = row[i]; s += v*v; }
    __shared__ float red[8];
    #pragma unroll
    for (int o = 16; o; o >>= 1) s += __shfl_xor_sync(0xffffffffu, s, o);
    if ((threadIdx.x & 31) == 0) red[threadIdx.x >> 5] = s;
    __syncthreads();
    if (threadIdx.x < 8) {
        float v = red[threadIdx.x];
        #pragma unroll
        for (int o = 4; o; o >>= 1) v += __shfl_xor_sync(0xffu, v, o);
        if (threadIdx.x == 0) red[0] = v;
    }
    __syncthreads();
    const float inv = rsqrtf(red[0]*(1.0f/H_) + 1e-6f);
    for (int i = threadIdx.x; i < H_; i += 256) out[(size_t)m*H_ + i] = row[i]*inv*w[i];
}

// ---------------- RoPE (in place, q & k via blockIdx.y) ----------------
__global__ void rope_kernel(float* __restrict__ qkv) {
    const int idx = blockIdx.x*256 + threadIdx.x;          // over M_*NH_*32
    if (idx >= M_*NH_*32) return;
    const int i  = idx & 31;
    const int nh = (idx >> 5) & 15;
    const int m  = idx >> 9;
    const int t  = m & (T_-1);
    float* base = qkv + (size_t)blockIdx.y*MH_ + (size_t)m*H_ + nh*HD_;
    const float x1 = base[i], x2 = base[i+32];
    const float inv = expf(-(float)i * (1.0f/32.0f) * 9.210340371976184f); // ln(10000)
    const float ang = (float)t * inv;
    const float c = cosf(ang), s = sinf(ang);
    base[i]    = x1*c - x2*s;
    base[i+32] = x2*c + x1*s;
}

// ---------------- flash attention (fp32, causal) ----------------
#define AQ 64
#define AK 32
__global__ void attn_kernel(const float* __restrict__ qkv, float* __restrict__ att) {
    const int qt = blockIdx.x, nh = blockIdx.y, b = blockIdx.z;
    const int tid = threadIdx.x;
    const int tx = tid & 15;
    const int ty = tid >> 4;
    __shared__ __align__(16) float Qs[AQ][HD_+4];
    __shared__ __align__(16) float Ks[AK][HD_+4];
    __shared__ __align__(16) float Vs[AK][HD_+4];
    __shared__ __align__(16) float Ps[AQ][AK+4];
    const size_t baseQ  = (size_t)(b*T_ + qt*AQ)*H_ + nh*HD_;
    const size_t baseKV = (size_t)(b*T_)*H_ + nh*HD_;
    const float* Qg = qkv + baseQ;
    const float* Kg = qkv + MH_   + baseKV;
    const float* Vg = qkv + 2*MH_ + baseKV;
    #pragma unroll
    for (int u = 0; u < 4; u++) {
        int q = tid + u*256;
        int r = q >> 4, c = (q & 15) << 2;
        *(float4*)(&Qs[r][c]) = *(const float4*)(Qg + (size_t)r*H_ + c);
    }
    float m_i[4], l_i[4], O[4][4];
    #pragma unroll
    for (int i = 0; i < 4; i++) {
        m_i[i] = -1e30f; l_i[i] = 0.f;
        #pragma unroll
        for (int j = 0; j < 4; j++) O[i][j] = 0.f;
    }
    const int nkv = 2*qt + 2;
    for (int kvt = 0; kvt < nkv; kvt++) {
        __syncthreads();
        #pragma unroll
        for (int u = 0; u < 2; u++) {
            int q = tid + u*256;
            int r = q >> 4, c = (q & 15) << 2;
            *(float4*)(&Ks[r][c]) = *(const float4*)(Kg + (size_t)(kvt*AK + r)*H_ + c);
            *(float4*)(&Vs[r][c]) = *(const float4*)(Vg + (size_t)(kvt*AK + r)*H_ + c);
        }
        __syncthreads();
        float s[4][2] = {};
        #pragma unroll
        for (int k4 = 0; k4 < HD_; k4 += 4) {
            float4 q0 = *(const float4*)&Qs[ty*4+0][k4];
            float4 q1 = *(const float4*)&Qs[ty*4+1][k4];
            float4 q2 = *(const float4*)&Qs[ty*4+2][k4];
            float4 q3 = *(const float4*)&Qs[ty*4+3][k4];
            float4 ka = *(const float4*)&Ks[tx*2+0][k4];
            float4 kb = *(const float4*)&Ks[tx*2+1][k4];
            s[0][0] += q0.x*ka.x + q0.y*ka.y + q0.z*ka.z + q0.w*ka.w;
            s[0][1] += q0.x*kb.x + q0.y*kb.y + q0.z*kb.z + q0.w*kb.w;
            s[1][0] += q1.x*ka.x + q1.y*ka.y + q1.z*ka.z + q1.w*ka.w;
            s[1][1] += q1.x*kb.x + q1.y*kb.y + q1.z*kb.z + q1.w*kb.w;
            s[2][0] += q2.x*ka.x + q2.y*ka.y + q2.z*ka.z + q2.w*ka.w;
            s[2][1] += q2.x*kb.x + q2.y*kb.y + q2.z*kb.z + q2.w*kb.w;
            s[3][0] += q3.x*ka.x + q3.y*ka.y + q3.z*ka.z + q3.w*ka.w;
            s[3][1] += q3.x*kb.x + q3.y*kb.y + q3.z*kb.z + q3.w*kb.w;
        }
        #pragma unroll
        for (int i = 0; i < 4; i++) {
            const int qrow = qt*AQ + ty*4 + i;
            #pragma unroll
            for (int j = 0; j < 2; j++) {
                const int kcol = kvt*AK + tx*2 + j;
                s[i][j] = (kcol <= qrow) ? s[i][j]*0.125f : -1e9f;
            }
        }
        #pragma unroll
        for (int i = 0; i < 4; i++) {
            float mx = fmaxf(s[i][0], s[i][1]);
            #pragma unroll
            for (int o = 8; o; o >>= 1) mx = fmaxf(mx, __shfl_xor_sync(0xffffffffu, mx, o));
            const float mn = fmaxf(m_i[i], mx);
            const float p0 = expf(s[i][0]-mn), p1 = expf(s[i][1]-mn);
            float rs = p0 + p1;
            #pragma unroll
            for (int o = 8; o; o >>= 1) rs += __shfl_xor_sync(0xffffffffu, rs, o);
            const float alpha = expf(m_i[i]-mn);
            m_i[i] = mn;
            l_i[i] = l_i[i]*alpha + rs;
            #pragma unroll
            for (int j = 0; j < 4; j++) O[i][j] *= alpha;
            Ps[ty*4+i][tx*2+0] = p0;
            Ps[ty*4+i][tx*2+1] = p1;
        }
        __syncthreads();
        #pragma unroll
        for (int k4 = 0; k4 < AK; k4 += 4) {
            float4 v0 = *(const float4*)&Vs[k4+0][tx*4];
            float4 v1 = *(const float4*)&Vs[k4+1][tx*4];
            float4 v2 = *(const float4*)&Vs[k4+2][tx*4];
            float4 v3 = *(const float4*)&Vs[k4+3][tx*4];
            #pragma unroll
            for (int i = 0; i < 4; i++) {
                float4 p = *(const float4*)&Ps[ty*4+i][k4];
                O[i][0] += p.x*v0.x + p.y*v1.x + p.z*v2.x + p.w*v3.x;
                O[i][1] += p.x*v0.y + p.y*v1.y + p.z*v2.y + p.w*v3.y;
                O[i][2] += p.x*v0.z + p.y*v1.z + p.z*v2.z + p.w*v3.z;
                O[i][3] += p.x*v0.w + p.y*v1.w + p.z*v2.w + p.w*v3.w;
            }
        }
    }
    #pragma unroll
    for (int i = 0; i < 4; i++) {
        const float invl = 1.0f/l_i[i];
        const size_t off = (size_t)(b*T_ + qt*AQ + ty*4 + i)*H_ + nh*HD_ + tx*4;
        float4 v = make_float4(O[i][0]*invl, O[i][1]*invl, O[i][2]*invl, O[i][3]*invl);
        *(float4*)(att + off) = v;
    }
}

// ---------------- tf32x3 GEMM: C[M,N] (+)= A[M,K] @ B[K,N] -------------------
// 3xTF32 split: x = hi + lo (both tf32); x*w = hi*hi + hi*lo + lo*hi (fp32-ish).
// Block 128x128, BK=16, 256 threads / 8 warps in 2(M)x4(N); warp tile 64x32.
#define GBM 128
#define GBN 128
#define GBK 16
#define GSTR 136   // smem row stride: 136 mod 32 == 8 -> conflict-free frags

__device__ __forceinline__ void split_tf32(float x, uint32_t& hi, uint32_t& lo) {
    asm("cvt.rna.tf32.f32 %0, %1;" : "=r"(hi) : "f"(x));
    float r = x - __uint_as_float(hi);
    asm("cvt.rna.tf32.f32 %0, %1;" : "=r"(lo) : "f"(r));
}

__device__ __forceinline__ void mma8(float& c0, float& c1, float& c2, float& c3,
                                     uint32_t a0, uint32_t a1, uint32_t a2, uint32_t a3,
                                     uint32_t b0, uint32_t b1) {
    asm volatile("mma.sync.aligned.m16n8k8.row.col.f32.tf32.tf32.f32 "
                 "{%0,%1,%2,%3}, {%4,%5,%6,%7}, {%8,%9}, {%0,%1,%2,%3};"
                 : "+f"(c0), "+f"(c1), "+f"(c2), "+f"(c3)
                 : "r"(a0), "r"(a1), "r"(a2), "r"(a3), "r"(b0), "r"(b1));
}

template<bool ADD>
__global__ void __launch_bounds__(256)
gemm_tf32_kernel(const float* __restrict__ A, const float* __restrict__ B,
                 float* __restrict__ C, int M, int N, int K,
                 size_t strideB, size_t strideC) {
    B += (size_t)blockIdx.z * strideB;
    C += (size_t)blockIdx.z * strideC;

    __shared__ uint32_t Asb[GBK*GSTR];   // A hi, [k][m]
    __shared__ uint32_t Asl[GBK*GSTR];   // A lo
    __shared__ uint32_t Bsb[GBK*GSTR];   // B hi, [k][n]
    __shared__ uint32_t Bsl[GBK*GSTR];   // B lo

    const int tid  = threadIdx.x;
    const int lane = tid & 31;
    const int wid  = tid >> 5;
    const int warp_m = wid & 1;          // 2 warps in M
    const int warp_n = wid >> 1;         // 4 warps in N
    const int g  = lane >> 2;
    const int tg = lane & 3;
    const int rbase = warp_m * 64;
    const int cbase = warp_n * 32;
    const int row0 = blockIdx.y * GBM;
    const int col0 = blockIdx.x * GBN;

    const float* Ap = A + (size_t)row0 * K;
    const float* Bp = B + col0;

    float acc[4][4][4];
    #pragma unroll
    for (int mt = 0; mt < 4; mt++)
        #pragma unroll
        for (int nt = 0; nt < 4; nt++)
            #pragma unroll
            for (int c = 0; c < 4; c++) acc[mt][nt][c] = 0.f;

    // prefetch tile 0 into registers
    float4 ra[2], rb[2];
    #pragma unroll
    for (int u = 0; u < 2; u++) {
        int q = tid + u*256;
        int ar = q >> 2, ac = (q & 3) << 2;
        ra[u] = *(const float4*)(Ap + (size_t)ar*K + ac);
        int br = q >> 5, bc = (q & 31) << 2;
        rb[u] = *(const float4*)(Bp + (size_t)br*N + bc);
    }

    for (int k0 = 0; k0 < K; k0 += GBK) {
        // stage prefetched tile into smem with tf32 split
        #pragma unroll
        for (int u = 0; u < 2; u++) {
            int q = tid + u*256;
            int ar = q >> 2, ac = (q & 3) << 2;
            float av[4] = {ra[u].x, ra[u].y, ra[u].z, ra[u].w};
            #pragma unroll
            for (int c = 0; c < 4; c++) {
                uint32_t hi, lo; split_tf32(av[c], hi, lo);
                Asb[(ac+c)*GSTR + ar] = hi;
                Asl[(ac+c)*GSTR + ar] = lo;
            }
            int br = q >> 5, bc = (q & 31) << 2;
            float bv[4] = {rb[u].x, rb[u].y, rb[u].z, rb[u].w};
            uint4 bh, blv;
            split_tf32(bv[0], bh.x, blv.x);
            split_tf32(bv[1], bh.y, blv.y);
            split_tf32(bv[2], bh.z, blv.z);
            split_tf32(bv[3], bh.w, blv.w);
            *(uint4*)(&Bsb[br*GSTR + bc]) = bh;
            *(uint4*)(&Bsl[br*GSTR + bc]) = blv;
        }
        __syncthreads();

        // prefetch next tile
        if (k0 + GBK < K) {
            #pragma unroll
            for (int u = 0; u < 2; u++) {
                int q = tid + u*256;
                int ar = q >> 2, ac = (q & 3) << 2;
                ra[u] = *(const float4*)(Ap + (size_t)ar*K + (k0 + GBK) + ac);
                int br = q >> 5, bc = (q & 31) << 2;
                rb[u] = *(const float4*)(Bp + (size_t)(k0 + GBK + br)*N + bc);
            }
        }

        // compute: 2 k-steps of m16n8k8
        #pragma unroll
        for (int ks = 0; ks < 2; ks++) {
            const int kk = ks*8;
            uint32_t bb[8], bl[8];
            #pragma unroll
            for (int nt = 0; nt < 4; nt++) {
                int c = cbase + nt*8 + g;
                bb[nt*2+0] = Bsb[(kk+tg  )*GSTR + c];
                bb[nt*2+1] = Bsb[(kk+tg+4)*GSTR + c];
                bl[nt*2+0] = Bsl[(kk+tg  )*GSTR + c];
                bl[nt*2+1] = Bsl[(kk+tg+4)*GSTR + c];
            }
            #pragma unroll
            for (int mt = 0; mt < 4; mt++) {
                int r = rbase + mt*16 + g;
                uint32_t ab0 = Asb[(kk+tg  )*GSTR + r];
                uint32_t ab1 = Asb[(kk+tg  )*GSTR + r + 8];
                uint32_t ab2 = Asb[(kk+tg+4)*GSTR + r];
                uint32_t ab3 = Asb[(kk+tg+4)*GSTR + r + 8];
                uint32_t al0 = Asl[(kk+tg  )*GSTR + r];
                uint32_t al1 = Asl[(kk+tg  )*GSTR + r + 8];
                uint32_t al2 = Asl[(kk+tg+4)*GSTR + r];
                uint32_t al3 = Asl[(kk+tg+4)*GSTR + r + 8];
                #pragma unroll
                for (int nt = 0; nt < 4; nt++) {
                    float* c4 = acc[mt][nt];
                    mma8(c4[0],c4[1],c4[2],c4[3], ab0,ab1,ab2,ab3, bb[nt*2], bb[nt*2+1]);
                    mma8(c4[0],c4[1],c4[2],c4[3], ab0,ab1,ab2,ab3, bl[nt*2], bl[nt*2+1]);
                    mma8(c4[0],c4[1],c4[2],c4[3], al0,al1,al2,al3, bb[nt*2], bb[nt*2+1]);
                }
            }
        }
        __syncthreads();
    }

    // epilogue
    #pragma unroll
    for (int mt = 0; mt < 4; mt++) {
        #pragma unroll
        for (int nt = 0; nt < 4; nt++) {
            const int row = row0 + rbase + mt*16 + g;
            const int col = col0 + cbase + nt*8 + 2*tg;
            float2 v0 = make_float2(acc[mt][nt][0], acc[mt][nt][1]);
            float2 v1 = make_float2(acc[mt][nt][2], acc[mt][nt][3]);
            float* p0 = C + (size_t)row*N + col;
            float* p1 = C + (size_t)(row+8)*N + col;
            if (ADD) {
                float2 o0 = *(const float2*)p0;
                float2 o1 = *(const float2*)p1;
                v0.x += o0.x; v0.y += o0.y;
                v1.x += o1.x; v1.y += o1.y;
            }
            *(float2*)p0 = v0;
            *(float2*)p1 = v1;
        }
    }
}

// ---------------- SwiGLU: act = silu(g) * u ----------------
__global__ void silu_kernel(const float* __restrict__ g, const float* __restrict__ u,
                            float* __restrict__ act, int n) {
    const int i = blockIdx.x*256 + threadIdx.x;
    if (i < n) {
        const float gv = g[i];
        act[i] = (gv / (1.0f + expf(-gv))) * u[i];
    }
}

// ---------------- head: logits = latent@W + b, clamp, softmax ----------------
__global__ void head_kernel(const float* __restrict__ latent, const float* __restrict__ W,
                            const float* __restrict__ bias, const float* __restrict__ temp,
                            float* __restrict__ out) {
    const int m = blockIdx.x;
    __shared__ float xs[H_];
    __shared__ float red[8][32];
    const float* row = latent + (size_t)m*H_;
    for (int i = threadIdx.x; i < H_; i += 256) xs[i] = row[i];
    __syncthreads();
    const int n  = threadIdx.x & 31;
    const int ch = threadIdx.x >> 5;
    float p = 0.f;
    if (n < 31) {
        const int k0 = ch*128;
        for (int k = k0; k < k0 + 128; k++) p += xs[k]*W[(size_t)k*31 + n];
    }
    red[ch][n] = p;
    __syncthreads();
    if (threadIdx.x < 32) {
        float v = 0.f;
        if (n < 31) {
            #pragma unroll
            for (int c = 0; c < 8; c++) v += red[c][n];
            v += bias[n];
            v = fminf(fmaxf(v, -10.0f), 10.0f);
            out[(size_t)M_*31 + (size_t)m*31 + n] = v;     // logits_clamped (2nd output)
        }
        const float t = *temp;
        float mx = (n < 31) ? v : -1e30f;
        #pragma unroll
        for (int o = 16; o; o >>= 1) mx = fmaxf(mx, __shfl_xor_sync(0xffffffffu, mx, o));
        const float ev = (n < 31) ? expf((v - mx)/t) : 0.f;
        float sm = ev;
        #pragma unroll
        for (int o = 16; o; o >>= 1) sm += __shfl_xor_sync(0xffffffffu, sm, o);
        if (n < 31) out[(size_t)m*31 + n] = ev/sm;         // portfolio_weights (1st output)
    }
}

// ---------------- launcher ----------------
extern "C" void kernel_launch(void* const* d_in, const int* in_sizes, int n_in,
                              void* d_out, int out_size) {
    (void)in_sizes; (void)n_in; (void)out_size;
    const float* x       = (const float*)d_in[0];
    const float* temp    = (const float*)d_in[1];
    const float* state_W = (const float*)d_in[2];
    const float* state_b = (const float*)d_in[3];
    const float* ln1     = (const float*)d_in[4];
    const float* ln2     = (const float*)d_in[5];
    const float* Wqkv    = (const float*)d_in[6];
    const float* Aqkv    = (const float*)d_in[7];
    const float* Bqkv    = (const float*)d_in[8];
    const float* Wo      = (const float*)d_in[9];
    const float* Ao      = (const float*)d_in[10];
    const float* Bo      = (const float*)d_in[11];
    const float* Wgu     = (const float*)d_in[12];
    const float* Agu     = (const float*)d_in[13];
    const float* Bgu     = (const float*)d_in[14];
    const float* Wd      = (const float*)d_in[15];
    const float* Ad      = (const float*)d_in[16];
    const float* Bd      = (const float*)d_in[17];
    const float* ln_f    = (const float*)d_in[18];
    const float* head_W  = (const float*)d_in[19];
    const float* head_b  = (const float*)d_in[20];
    float* out = (float*)d_out;

    float *p_h, *p_hn, *p_qkv, *p_att, *p_gu, *p_act, *pWq, *pWo, *pWgu, *pWd;
    cudaGetSymbolAddress((void**)&p_h,   g_h);
    cudaGetSymbolAddress((void**)&p_hn,  g_hn);
    cudaGetSymbolAddress((void**)&p_qkv, g_qkv);
    cudaGetSymbolAddress((void**)&p_att, g_att);
    cudaGetSymbolAddress((void**)&p_gu,  g_gu);
    cudaGetSymbolAddress((void**)&p_act, g_act);
    cudaGetSymbolAddress((void**)&pWq,   g_Wq);
    cudaGetSymbolAddress((void**)&pWo,   g_Wo_);
    cudaGetSymbolAddress((void**)&pWgu,  g_Wgu);
    cudaGetSymbolAddress((void**)&pWd,   g_Wd_);

    // ---- fold LoRA into effective weights (memory-roofline version) ----
    fuse_lora2_kernel<<<dim3(4,  32, 24), 256>>>(Wqkv, Aqkv, Bqkv, pWq,  H_, H_);
    fuse_lora2_kernel<<<dim3(4,  32,  8), 256>>>(Wo,   Ao,   Bo,   pWo,  H_, H_);
    fuse_lora2_kernel<<<dim3(11, 32, 16), 256>>>(Wgu,  Agu,  Bgu,  pWgu, H_, F_);
    fuse_lora2_kernel<<<dim3(4,  88,  8), 256>>>(Wd,   Ad,   Bd,   pWd,  F_, H_);

    // ---- embed ----
    init_h_kernel<<<dim3(4, M_), 256>>>(x, state_W, state_b);

    // ---- layers ----
    for (int l = 0; l < L_; l++) {
        rms_kernel<<<M_, 256>>>(p_h, ln1 + (size_t)l*H_, p_hn);
        gemm_tf32_kernel<false><<<dim3(8, 16, 3), 256>>>(p_hn, pWq + (size_t)l*3*HH_, p_qkv,
                                                         M_, H_, H_, HH_, MH_);
        rope_kernel<<<dim3(4096, 2), 256>>>(p_qkv);
        attn_kernel<<<dim3(16, 16, 2), 256>>>(p_qkv, p_att);
        gemm_tf32_kernel<true><<<dim3(8, 16, 1), 256>>>(p_att, pWo + (size_t)l*HH_, p_h,
                                                        M_, H_, H_, 0, 0);
        rms_kernel<<<M_, 256>>>(p_h, ln2 + (size_t)l*H_, p_hn);
        gemm_tf32_kernel<false><<<dim3(22, 16, 2), 256>>>(p_hn, pWgu + (size_t)l*2*HF_, p_gu,
                                                          M_, F_, H_, HF_, MF_);
        silu_kernel<<<(int)((MF_ + 255)/256), 256>>>(p_gu, p_gu + MF_, p_act, (int)MF_);
        gemm_tf32_kernel<true><<<dim3(8, 16, 1), 256>>>(p_act, pWd + (size_t)l*HF_, p_h,
                                                        M_, H_, F_, 0, 0);
    }

    // ---- final norm + head + softmax ----
    rms_kernel<<<M_, 256>>>(p_h, ln_f, p_hn);
    head_kernel<<<M_, 256>>>(p_hn, head_W, head_b, temp, out);
}

// round 10
// speedup vs baseline: 2.1893x; 1.6582x over previous
#include <cuda_runtime.h>
#include <cuda_bf16.h>
#include <math.h>
#include <stdint.h>

// ---------------- problem constants ----------------
#define B_   2
#define T_   1024
#define NT_  30
#define H_   1024
#define L_   8
#define F_   2816
#define NH_  16
#define HD_  64
#define R_   16
#define M_   (B_*T_)                 // 2048 tokens
#define MH_  ((size_t)M_*H_)
#define HH_  ((size_t)H_*H_)
#define HF_  ((size_t)H_*F_)
#define MF_  ((size_t)M_*F_)

// ---------------- scratch (device globals: no allocation allowed) ----------------
__device__ float g_h  [M_*H_];       // fp32 residual stream
__device__ float g_hn [M_*H_];       // fp32 rms out (head input)
__device__ float g_qkv[3*M_*H_];
__device__ float g_gu [2*M_*F_];
// bf16 hi/lo activation operands
__device__ __nv_bfloat16 g_hn_hi [M_*H_], g_hn_lo [M_*H_];
__device__ __nv_bfloat16 g_att_hi[M_*H_], g_att_lo[M_*H_];
__device__ __nv_bfloat16 g_act_hi[M_*F_], g_act_lo[M_*F_];
// fused+TRANSPOSED effective weights as bf16 hi/lo: W_T[n][k]
__device__ __nv_bfloat16 g_Wq_hi [L_*3*H_*H_], g_Wq_lo [L_*3*H_*H_];
__device__ __nv_bfloat16 g_Wo_hi [L_*H_*H_],   g_Wo_lo [L_*H_*H_];
__device__ __nv_bfloat16 g_Wgu_hi[L_*2*H_*F_], g_Wgu_lo[L_*2*H_*F_];
__device__ __nv_bfloat16 g_Wd_hi [L_*F_*H_],   g_Wd_lo [L_*F_*H_];

// ---------------- helpers ----------------
__device__ __forceinline__ uint32_t s2u(const void* p) {
    uint32_t a;
    asm("{ .reg .u64 t; cvta.to.shared.u64 t, %1; cvt.u32.u64 %0, t; }" : "=r"(a) : "l"(p));
    return a;
}
__device__ __forceinline__ void bsplit(float v, __nv_bfloat16& h, __nv_bfloat16& l) {
    h = __float2bfloat16(v);
    l = __float2bfloat16(v - __bfloat162float(h));
}
__device__ __forceinline__ void cpa16(uint32_t s, const void* g) {
    asm volatile("cp.async.ca.shared.global [%0], [%1], 16;" :: "r"(s), "l"(g) : "memory");
}
__device__ __forceinline__ void cp_commit() {
    asm volatile("cp.async.commit_group;" ::: "memory");
}
template<int NN> __device__ __forceinline__ void cp_wait() {
    asm volatile("cp.async.wait_group %0;" :: "n"(NN) : "memory");
}
__device__ __forceinline__ void mma16816(float* c, const uint32_t* a, const uint32_t* b) {
    asm volatile("mma.sync.aligned.m16n8k16.row.col.f32.bf16.bf16.f32 "
        "{%0,%1,%2,%3}, {%4,%5,%6,%7}, {%8,%9}, {%0,%1,%2,%3};"
        : "+f"(c[0]), "+f"(c[1]), "+f"(c[2]), "+f"(c[3])
        : "r"(a[0]), "r"(a[1]), "r"(a[2]), "r"(a[3]), "r"(b[0]), "r"(b[1]));
}

// ============ bf16x3 tensor-core GEMM: C[M,N] (+)= A @ B^T ============
// A (act): [M,K] bf16 hi/lo row-major.  B (weightT): [N,K] bf16 hi/lo row-major.
// CTA 128x128, BK=32 (16 k-pairs), 256 thr / 8 warps (2Mx4N), warp tile 64x32.
// smem per stage (uint32): Ah[128][20] Al[128][20] Bh[128][20] Bl[128][20]
#define TSTR 20
#define TILE_U32 (128*TSTR)          // 2560
#define STAGE_U32 (4*TILE_U32)       // 10240
#define GSMEM_BYTES (2*STAGE_U32*4)  // 81920

template<bool ADD>
__global__ void __launch_bounds__(256)
gemm_bf16x3(const __nv_bfloat16* __restrict__ Ahi, const __nv_bfloat16* __restrict__ Alo,
            const __nv_bfloat16* __restrict__ Bhi, const __nv_bfloat16* __restrict__ Blo,
            float* __restrict__ C, int N, int K, size_t strideB, size_t strideC)
{
    extern __shared__ uint32_t smu[];
    Bhi += (size_t)blockIdx.z * strideB;
    Blo += (size_t)blockIdx.z * strideB;
    C   += (size_t)blockIdx.z * strideC;

    const int tid  = threadIdx.x;
    const int lane = tid & 31;
    const int wid  = tid >> 5;
    const int g    = lane >> 2;      // 0..7
    const int tg   = lane & 3;       // 0..3
    const int rbase = (wid & 1) * 64;
    const int cbase = (wid >> 1) * 32;
    const int row0 = blockIdx.y * 128;
    const int col0 = blockIdx.x * 128;

    const uint32_t smb = s2u(smu);
    const int ld_m  = tid >> 2;      // 0..63 (+64 for u=1)
    const int ld_kc = tid & 3;       // 16B chunk within 64B row-chunk

    auto load_stage = [&](int st, int ch) {
        const uint32_t base = smb + (uint32_t)st * (STAGE_U32 * 4);
        #pragma unroll
        for (int u = 0; u < 2; u++) {
            const int m = ld_m + u * 64;
            const size_t ga = (size_t)(row0 + m) * K + ch * 32 + ld_kc * 8;
            const size_t gb = (size_t)(col0 + m) * K + ch * 32 + ld_kc * 8;
            const uint32_t so = (uint32_t)(m * TSTR + ld_kc * 4) * 4;
            cpa16(base +                  so, Ahi + ga);
            cpa16(base + TILE_U32*4     + so, Alo + ga);
            cpa16(base + 2*TILE_U32*4   + so, Bhi + gb);
            cpa16(base + 3*TILE_U32*4   + so, Blo + gb);
        }
        cp_commit();
    };

    float acc[4][4][4];
    #pragma unroll
    for (int mt = 0; mt < 4; mt++)
        #pragma unroll
        for (int nt = 0; nt < 4; nt++)
            #pragma unroll
            for (int c = 0; c < 4; c++) acc[mt][nt][c] = 0.f;

    const int nch = K / 32;
    load_stage(0, 0);

    for (int ch = 0; ch < nch; ch++) {
        const int st = ch & 1;
        if (ch + 1 < nch) { load_stage(st ^ 1, ch + 1); cp_wait<1>(); }
        else              { cp_wait<0>(); }
        __syncthreads();

        const uint32_t* Ah = smu + st * STAGE_U32;
        const uint32_t* Al = Ah + TILE_U32;
        const uint32_t* Bh = Ah + 2 * TILE_U32;
        const uint32_t* Bl = Ah + 3 * TILE_U32;

        #pragma unroll
        for (int ks = 0; ks < 2; ks++) {
            const int kb = ks * 8 + tg;
            uint32_t bh[4][2], bl[4][2];
            #pragma unroll
            for (int nt = 0; nt < 4; nt++) {
                const int n = cbase + nt * 8 + g;
                bh[nt][0] = Bh[n * TSTR + kb];
                bh[nt][1] = Bh[n * TSTR + kb + 4];
                bl[nt][0] = Bl[n * TSTR + kb];
                bl[nt][1] = Bl[n * TSTR + kb + 4];
            }
            #pragma unroll
            for (int mt = 0; mt < 4; mt++) {
                const int r = rbase + mt * 16 + g;
                uint32_t ah[4], al[4];
                ah[0] = Ah[ r      * TSTR + kb];
                ah[1] = Ah[(r + 8) * TSTR + kb];
                ah[2] = Ah[ r      * TSTR + kb + 4];
                ah[3] = Ah[(r + 8) * TSTR + kb + 4];
                al[0] = Al[ r      * TSTR + kb];
                al[1] = Al[(r + 8) * TSTR + kb];
                al[2] = Al[ r      * TSTR + kb + 4];
                al[3] = Al[(r + 8) * TSTR + kb + 4];
                #pragma unroll
                for (int nt = 0; nt < 4; nt++) {
                    mma16816(acc[mt][nt], ah, bh[nt]);
                    mma16816(acc[mt][nt], ah, bl[nt]);
                    mma16816(acc[mt][nt], al, bh[nt]);
                }
            }
        }
        __syncthreads();
    }

    // epilogue: c0,c1 -> (row, col..col+1); c2,c3 -> (row+8, ...)
    #pragma unroll
    for (int mt = 0; mt < 4; mt++) {
        #pragma unroll
        for (int nt = 0; nt < 4; nt++) {
            const int row = row0 + rbase + mt * 16 + g;
            const int col = col0 + cbase + nt * 8 + 2 * tg;
            float2 v0 = make_float2(acc[mt][nt][0], acc[mt][nt][1]);
            float2 v1 = make_float2(acc[mt][nt][2], acc[mt][nt][3]);
            float* p0 = C + (size_t)row * N + col;
            float* p1 = C + (size_t)(row + 8) * N + col;
            if (ADD) {
                float2 o0 = *(const float2*)p0;
                float2 o1 = *(const float2*)p1;
                v0.x += o0.x; v0.y += o0.y;
                v1.x += o1.x; v1.y += o1.y;
            }
            *(float2*)p0 = v0;
            *(float2*)p1 = v1;
        }
    }
}

// ---------------- LoRA fold: WeffT[n][k] (bf16 hi/lo) ----------------
__global__ void fold_kernel(const float* __restrict__ W, const float* __restrict__ A,
                            const float* __restrict__ Bm,
                            __nv_bfloat16* __restrict__ Whi, __nv_bfloat16* __restrict__ Wlo,
                            int KK, int N) {
    const int mat = blockIdx.z;
    const int i0 = blockIdx.x * 32, j0 = blockIdx.y * 32;
    W   += (size_t)mat * KK * N;
    A   += (size_t)mat * R_ * KK;
    Bm  += (size_t)mat * N * R_;
    Whi += (size_t)mat * (size_t)KK * N;
    Wlo += (size_t)mat * (size_t)KK * N;

    __shared__ float Wt[32][33];
    __shared__ float As[R_][33];
    __shared__ float Bs[32][R_+1];
    const int tx = threadIdx.x & 31, ty = threadIdx.x >> 5;   // 32 x 8
    #pragma unroll
    for (int u = 0; u < 4; u++) {
        int ii = ty * 4 + u;
        Wt[ii][tx] = W[(size_t)(i0 + ii) * N + j0 + tx];
    }
    #pragma unroll
    for (int u = 0; u < 2; u++) {
        int id = threadIdx.x + u * 256;
        As[id >> 5][id & 31] = A[(size_t)(id >> 5) * KK + i0 + (id & 31)];
    }
    #pragma unroll
    for (int u = 0; u < 2; u++) {
        int id = threadIdx.x + u * 256;
        Bs[id >> 4][id & 15] = Bm[(size_t)(j0 + (id >> 4)) * R_ + (id & 15)];
    }
    __syncthreads();
    #pragma unroll
    for (int u = 0; u < 4; u++) {
        int jj = ty * 4 + u;
        float s = 0.f;
        #pragma unroll
        for (int r = 0; r < R_; r++) s += As[r][tx] * Bs[jj][r];
        float v = Wt[tx][jj] + 2.0f * s;
        __nv_bfloat16 h, l; bsplit(v, h, l);
        size_t off = (size_t)(j0 + jj) * KK + i0 + tx;
        Whi[off] = h; Wlo[off] = l;
    }
}

// ---------------- h = x @ state_W + state_b ----------------
__global__ void init_h_kernel(const float* __restrict__ x, const float* __restrict__ W,
                              const float* __restrict__ b) {
    const int m = blockIdx.y;
    const int j = blockIdx.x*256 + threadIdx.x;
    __shared__ float xs[NT_];
    if (threadIdx.x < NT_) xs[threadIdx.x] = x[(size_t)m*NT_ + threadIdx.x];
    __syncthreads();
    float s = b[j];
    #pragma unroll
    for (int k = 0; k < NT_; k++) s += xs[k]*W[(size_t)k*H_ + j];
    g_h[(size_t)m*H_ + j] = s;
}

// ---------------- RMSNorm (fp32 out + bf16 hi/lo out) ----------------
__global__ void rms_kernel(const float* __restrict__ in, const float* __restrict__ w,
                           float* __restrict__ out,
                           __nv_bfloat16* __restrict__ ohi, __nv_bfloat16* __restrict__ olo) {
    const int m = blockIdx.x;
    const float* row = in + (size_t)m*H_;
    float s = 0.f;
    for (int i = threadIdx.x; i < H_; i += 256) { float v = row[i]; s += v*v; }
    __shared__ float red[8];
    #pragma unroll
    for (int o = 16; o; o >>= 1) s += __shfl_xor_sync(0xffffffffu, s, o);
    if ((threadIdx.x & 31) == 0) red[threadIdx.x >> 5] = s;
    __syncthreads();
    if (threadIdx.x < 8) {
        float v = red[threadIdx.x];
        #pragma unroll
        for (int o = 4; o; o >>= 1) v += __shfl_xor_sync(0xffu, v, o);
        if (threadIdx.x == 0) red[0] = v;
    }
    __syncthreads();
    const float inv = rsqrtf(red[0]*(1.0f/H_) + 1e-6f);
    for (int i = threadIdx.x; i < H_; i += 256) {
        float v = row[i]*inv*w[i];
        out[(size_t)m*H_ + i] = v;
        __nv_bfloat16 h, l; bsplit(v, h, l);
        ohi[(size_t)m*H_ + i] = h;
        olo[(size_t)m*H_ + i] = l;
    }
}

// ---------------- RoPE (in place, q & k via blockIdx.y) ----------------
__global__ void rope_kernel(float* __restrict__ qkv) {
    const int idx = blockIdx.x*256 + threadIdx.x;
    if (idx >= M_*NH_*32) return;
    const int i  = idx & 31;
    const int nh = (idx >> 5) & 15;
    const int m  = idx >> 9;
    const int t  = m & (T_-1);
    float* base = qkv + (size_t)blockIdx.y*MH_ + (size_t)m*H_ + nh*HD_;
    const float x1 = base[i], x2 = base[i+32];
    const float inv = expf(-(float)i * (1.0f/32.0f) * 9.210340371976184f);
    const float ang = (float)t * inv;
    const float c = cosf(ang), sn = sinf(ang);
    base[i]    = x1*c - x2*sn;
    base[i+32] = x2*c + x1*sn;
}

// ---------------- flash attention (fp32, causal) -> bf16 hi/lo out ----------------
#define AQ 64
#define AK 32
__global__ void attn_kernel(const float* __restrict__ qkv,
                            __nv_bfloat16* __restrict__ att_hi,
                            __nv_bfloat16* __restrict__ att_lo) {
    const int qt = blockIdx.x, nh = blockIdx.y, b = blockIdx.z;
    const int tid = threadIdx.x;
    const int tx = tid & 15;
    const int ty = tid >> 4;
    __shared__ __align__(16) float Qs[AQ][HD_+4];
    __shared__ __align__(16) float Ks[AK][HD_+4];
    __shared__ __align__(16) float Vs[AK][HD_+4];
    __shared__ __align__(16) float Ps[AQ][AK+4];
    const size_t baseQ  = (size_t)(b*T_ + qt*AQ)*H_ + nh*HD_;
    const size_t baseKV = (size_t)(b*T_)*H_ + nh*HD_;
    const float* Qg = qkv + baseQ;
    const float* Kg = qkv + MH_   + baseKV;
    const float* Vg = qkv + 2*MH_ + baseKV;
    #pragma unroll
    for (int u = 0; u < 4; u++) {
        int q = tid + u*256;
        int r = q >> 4, c = (q & 15) << 2;
        *(float4*)(&Qs[r][c]) = *(const float4*)(Qg + (size_t)r*H_ + c);
    }
    float m_i[4], l_i[4], O[4][4];
    #pragma unroll
    for (int i = 0; i < 4; i++) {
        m_i[i] = -1e30f; l_i[i] = 0.f;
        #pragma unroll
        for (int j = 0; j < 4; j++) O[i][j] = 0.f;
    }
    const int nkv = 2*qt + 2;
    for (int kvt = 0; kvt < nkv; kvt++) {
        __syncthreads();
        #pragma unroll
        for (int u = 0; u < 2; u++) {
            int q = tid + u*256;
            int r = q >> 4, c = (q & 15) << 2;
            *(float4*)(&Ks[r][c]) = *(const float4*)(Kg + (size_t)(kvt*AK + r)*H_ + c);
            *(float4*)(&Vs[r][c]) = *(const float4*)(Vg + (size_t)(kvt*AK + r)*H_ + c);
        }
        __syncthreads();
        float s[4][2] = {};
        #pragma unroll
        for (int k4 = 0; k4 < HD_; k4 += 4) {
            float4 q0 = *(const float4*)&Qs[ty*4+0][k4];
            float4 q1 = *(const float4*)&Qs[ty*4+1][k4];
            float4 q2 = *(const float4*)&Qs[ty*4+2][k4];
            float4 q3 = *(const float4*)&Qs[ty*4+3][k4];
            float4 ka = *(const float4*)&Ks[tx*2+0][k4];
            float4 kb = *(const float4*)&Ks[tx*2+1][k4];
            s[0][0] += q0.x*ka.x + q0.y*ka.y + q0.z*ka.z + q0.w*ka.w;
            s[0][1] += q0.x*kb.x + q0.y*kb.y + q0.z*kb.z + q0.w*kb.w;
            s[1][0] += q1.x*ka.x + q1.y*ka.y + q1.z*ka.z + q1.w*ka.w;
            s[1][1] += q1.x*kb.x + q1.y*kb.y + q1.z*kb.z + q1.w*kb.w;
            s[2][0] += q2.x*ka.x + q2.y*ka.y + q2.z*ka.z + q2.w*ka.w;
            s[2][1] += q2.x*kb.x + q2.y*kb.y + q2.z*kb.z + q2.w*kb.w;
            s[3][0] += q3.x*ka.x + q3.y*ka.y + q3.z*ka.z + q3.w*ka.w;
            s[3][1] += q3.x*kb.x + q3.y*kb.y + q3.z*kb.z + q3.w*kb.w;
        }
        #pragma unroll
        for (int i = 0; i < 4; i++) {
            const int qrow = qt*AQ + ty*4 + i;
            #pragma unroll
            for (int j = 0; j < 2; j++) {
                const int kcol = kvt*AK + tx*2 + j;
                s[i][j] = (kcol <= qrow) ? s[i][j]*0.125f : -1e9f;
            }
        }
        #pragma unroll
        for (int i = 0; i < 4; i++) {
            float mx = fmaxf(s[i][0], s[i][1]);
            #pragma unroll
            for (int o = 8; o; o >>= 1) mx = fmaxf(mx, __shfl_xor_sync(0xffffffffu, mx, o));
            const float mn = fmaxf(m_i[i], mx);
            const float p0 = expf(s[i][0]-mn), p1 = expf(s[i][1]-mn);
            float rs = p0 + p1;
            #pragma unroll
            for (int o = 8; o; o >>= 1) rs += __shfl_xor_sync(0xffffffffu, rs, o);
            const float alpha = expf(m_i[i]-mn);
            m_i[i] = mn;
            l_i[i] = l_i[i]*alpha + rs;
            #pragma unroll
            for (int j = 0; j < 4; j++) O[i][j] *= alpha;
            Ps[ty*4+i][tx*2+0] = p0;
            Ps[ty*4+i][tx*2+1] = p1;
        }
        __syncthreads();
        #pragma unroll
        for (int k4 = 0; k4 < AK; k4 += 4) {
            float4 v0 = *(const float4*)&Vs[k4+0][tx*4];
            float4 v1 = *(const float4*)&Vs[k4+1][tx*4];
            float4 v2 = *(const float4*)&Vs[k4+2][tx*4];
            float4 v3 = *(const float4*)&Vs[k4+3][tx*4];
            #pragma unroll
            for (int i = 0; i < 4; i++) {
                float4 p = *(const float4*)&Ps[ty*4+i][k4];
                O[i][0] += p.x*v0.x + p.y*v1.x + p.z*v2.x + p.w*v3.x;
                O[i][1] += p.x*v0.y + p.y*v1.y + p.z*v2.y + p.w*v3.y;
                O[i][2] += p.x*v0.z + p.y*v1.z + p.z*v2.z + p.w*v3.z;
                O[i][3] += p.x*v0.w + p.y*v1.w + p.z*v2.w + p.w*v3.w;
            }
        }
    }
    #pragma unroll
    for (int i = 0; i < 4; i++) {
        const float invl = 1.0f/l_i[i];
        const size_t off = (size_t)(b*T_ + qt*AQ + ty*4 + i)*H_ + nh*HD_ + tx*4;
        #pragma unroll
        for (int j = 0; j < 4; j++) {
            float v = O[i][j]*invl;
            __nv_bfloat16 h, l; bsplit(v, h, l);
            att_hi[off + j] = h;
            att_lo[off + j] = l;
        }
    }
}

// ---------------- SwiGLU: act = silu(g) * u -> bf16 hi/lo ----------------
__global__ void silu_kernel(const float* __restrict__ g, const float* __restrict__ u,
                            __nv_bfloat16* __restrict__ ahi, __nv_bfloat16* __restrict__ alo,
                            int n) {
    const int i = blockIdx.x*256 + threadIdx.x;
    if (i < n) {
        const float gv = g[i];
        float v = (gv / (1.0f + expf(-gv))) * u[i];
        __nv_bfloat16 h, l; bsplit(v, h, l);
        ahi[i] = h; alo[i] = l;
    }
}

// ---------------- head: logits = latent@W + b, clamp, softmax ----------------
__global__ void head_kernel(const float* __restrict__ latent, const float* __restrict__ W,
                            const float* __restrict__ bias, const float* __restrict__ temp,
                            float* __restrict__ out) {
    const int m = blockIdx.x;
    __shared__ float xs[H_];
    __shared__ float red[8][32];
    const float* row = latent + (size_t)m*H_;
    for (int i = threadIdx.x; i < H_; i += 256) xs[i] = row[i];
    __syncthreads();
    const int n  = threadIdx.x & 31;
    const int ch = threadIdx.x >> 5;
    float p = 0.f;
    if (n < 31) {
        const int k0 = ch*128;
        for (int k = k0; k < k0 + 128; k++) p += xs[k]*W[(size_t)k*31 + n];
    }
    red[ch][n] = p;
    __syncthreads();
    if (threadIdx.x < 32) {
        float v = 0.f;
        if (n < 31) {
            #pragma unroll
            for (int c = 0; c < 8; c++) v += red[c][n];
            v += bias[n];
            v = fminf(fmaxf(v, -10.0f), 10.0f);
            out[(size_t)M_*31 + (size_t)m*31 + n] = v;
        }
        const float t = *temp;
        float mx = (n < 31) ? v : -1e30f;
        #pragma unroll
        for (int o = 16; o; o >>= 1) mx = fmaxf(mx, __shfl_xor_sync(0xffffffffu, mx, o));
        const float ev = (n < 31) ? expf((v - mx)/t) : 0.f;
        float sm = ev;
        #pragma unroll
        for (int o = 16; o; o >>= 1) sm += __shfl_xor_sync(0xffffffffu, sm, o);
        if (n < 31) out[(size_t)m*31 + n] = ev/sm;
    }
}

// ---------------- launcher ----------------
extern "C" void kernel_launch(void* const* d_in, const int* in_sizes, int n_in,
                              void* d_out, int out_size) {
    (void)in_sizes; (void)n_in; (void)out_size;
    const float* x       = (const float*)d_in[0];
    const float* temp    = (const float*)d_in[1];
    const float* state_W = (const float*)d_in[2];
    const float* state_b = (const float*)d_in[3];
    const float* ln1     = (const float*)d_in[4];
    const float* ln2     = (const float*)d_in[5];
    const float* Wqkv    = (const float*)d_in[6];
    const float* Aqkv    = (const float*)d_in[7];
    const float* Bqkv    = (const float*)d_in[8];
    const float* Wo      = (const float*)d_in[9];
    const float* Ao      = (const float*)d_in[10];
    const float* Bo      = (const float*)d_in[11];
    const float* Wgu     = (const float*)d_in[12];
    const float* Agu     = (const float*)d_in[13];
    const float* Bgu     = (const float*)d_in[14];
    const float* Wd      = (const float*)d_in[15];
    const float* Ad      = (const float*)d_in[16];
    const float* Bd      = (const float*)d_in[17];
    const float* ln_f    = (const float*)d_in[18];
    const float* head_W  = (const float*)d_in[19];
    const float* head_b  = (const float*)d_in[20];
    float* out = (float*)d_out;

    float *p_h, *p_hn, *p_qkv, *p_gu;
    __nv_bfloat16 *p_hn_hi, *p_hn_lo, *p_att_hi, *p_att_lo, *p_act_hi, *p_act_lo;
    __nv_bfloat16 *pWq_hi, *pWq_lo, *pWo_hi, *pWo_lo, *pWgu_hi, *pWgu_lo, *pWd_hi, *pWd_lo;
    cudaGetSymbolAddress((void**)&p_h,     g_h);
    cudaGetSymbolAddress((void**)&p_hn,    g_hn);
    cudaGetSymbolAddress((void**)&p_qkv,   g_qkv);
    cudaGetSymbolAddress((void**)&p_gu,    g_gu);
    cudaGetSymbolAddress((void**)&p_hn_hi, g_hn_hi);
    cudaGetSymbolAddress((void**)&p_hn_lo, g_hn_lo);
    cudaGetSymbolAddress((void**)&p_att_hi,g_att_hi);
    cudaGetSymbolAddress((void**)&p_att_lo,g_att_lo);
    cudaGetSymbolAddress((void**)&p_act_hi,g_act_hi);
    cudaGetSymbolAddress((void**)&p_act_lo,g_act_lo);
    cudaGetSymbolAddress((void**)&pWq_hi,  g_Wq_hi);
    cudaGetSymbolAddress((void**)&pWq_lo,  g_Wq_lo);
    cudaGetSymbolAddress((void**)&pWo_hi,  g_Wo_hi);
    cudaGetSymbolAddress((void**)&pWo_lo,  g_Wo_lo);
    cudaGetSymbolAddress((void**)&pWgu_hi, g_Wgu_hi);
    cudaGetSymbolAddress((void**)&pWgu_lo, g_Wgu_lo);
    cudaGetSymbolAddress((void**)&pWd_hi,  g_Wd_hi);
    cudaGetSymbolAddress((void**)&pWd_lo,  g_Wd_lo);

    cudaFuncSetAttribute(gemm_bf16x3<false>, cudaFuncAttributeMaxDynamicSharedMemorySize, GSMEM_BYTES);
    cudaFuncSetAttribute(gemm_bf16x3<true>,  cudaFuncAttributeMaxDynamicSharedMemorySize, GSMEM_BYTES);

    // ---- fold LoRA + transpose + bf16-split effective weights ----
    fold_kernel<<<dim3(32, 32, 24), 256>>>(Wqkv, Aqkv, Bqkv, pWq_hi,  pWq_lo,  H_, H_);
    fold_kernel<<<dim3(32, 32,  8), 256>>>(Wo,   Ao,   Bo,   pWo_hi,  pWo_lo,  H_, H_);
    fold_kernel<<<dim3(32, 88, 16), 256>>>(Wgu,  Agu,  Bgu,  pWgu_hi, pWgu_lo, H_, F_);
    fold_kernel<<<dim3(88, 32,  8), 256>>>(Wd,   Ad,   Bd,   pWd_hi,  pWd_lo,  F_, H_);

    // ---- embed ----
    init_h_kernel<<<dim3(4, M_), 256>>>(x, state_W, state_b);

    // ---- layers ----
    for (int l = 0; l < L_; l++) {
        rms_kernel<<<M_, 256>>>(p_h, ln1 + (size_t)l*H_, p_hn, p_hn_hi, p_hn_lo);
        gemm_bf16x3<false><<<dim3(8, 16, 3), 256, GSMEM_BYTES>>>(
            p_hn_hi, p_hn_lo, pWq_hi + (size_t)l*3*HH_, pWq_lo + (size_t)l*3*HH_,
            p_qkv, H_, H_, HH_, MH_);
        rope_kernel<<<dim3(4096, 2), 256>>>(p_qkv);
        attn_kernel<<<dim3(16, 16, 2), 256>>>(p_qkv, p_att_hi, p_att_lo);
        gemm_bf16x3<true><<<dim3(8, 16, 1), 256, GSMEM_BYTES>>>(
            p_att_hi, p_att_lo, pWo_hi + (size_t)l*HH_, pWo_lo + (size_t)l*HH_,
            p_h, H_, H_, 0, 0);
        rms_kernel<<<M_, 256>>>(p_h, ln2 + (size_t)l*H_, p_hn, p_hn_hi, p_hn_lo);
        gemm_bf16x3<false><<<dim3(22, 16, 2), 256, GSMEM_BYTES>>>(
            p_hn_hi, p_hn_lo, pWgu_hi + (size_t)l*2*HF_, pWgu_lo + (size_t)l*2*HF_,
            p_gu, F_, H_, HF_, MF_);
        silu_kernel<<<(int)((MF_ + 255)/256), 256>>>(p_gu, p_gu + MF_, p_act_hi, p_act_lo, (int)MF_);
        gemm_bf16x3<true><<<dim3(8, 16, 1), 256, GSMEM_BYTES>>>(
            p_act_hi, p_act_lo, pWd_hi + (size_t)l*HF_, pWd_lo + (size_t)l*HF_,
            p_h, H_, F_, 0, 0);
    }

    // ---- final norm + head + softmax ----
    rms_kernel<<<M_, 256>>>(p_h, ln_f, p_hn, p_hn_hi, p_hn_lo);
    head_kernel<<<M_, 256>>>(p_hn, head_W, head_b, temp, out);
}

// round 11
// speedup vs baseline: 2.3502x; 1.0735x over previous
#include <cuda_runtime.h>
#include <cuda_bf16.h>
#include <math.h>
#include <stdint.h>

// ---------------- problem constants ----------------
#define B_   2
#define T_   1024
#define NT_  30
#define H_   1024
#define L_   8
#define F_   2816
#define NH_  16
#define HD_  64
#define R_   16
#define M_   (B_*T_)                 // 2048 tokens
#define MH_  ((size_t)M_*H_)
#define HH_  ((size_t)H_*H_)
#define HF_  ((size_t)H_*F_)
#define MF_  ((size_t)M_*F_)

// ---------------- scratch (device globals: no allocation allowed) ----------------
__device__ float g_h  [M_*H_];       // fp32 residual stream
__device__ float g_hn [M_*H_];       // fp32 rms out (head input)
__device__ float g_qkv[3*M_*H_];
__device__ float g_gu [2*M_*F_];
// bf16 hi/lo activation operands
__device__ __nv_bfloat16 g_hn_hi [M_*H_], g_hn_lo [M_*H_];
__device__ __nv_bfloat16 g_att_hi[M_*H_], g_att_lo[M_*H_];
__device__ __nv_bfloat16 g_act_hi[M_*F_], g_act_lo[M_*F_];
// fused+TRANSPOSED effective weights as bf16 hi/lo: W_T[n][k]
__device__ __nv_bfloat16 g_Wq_hi [L_*3*H_*H_], g_Wq_lo [L_*3*H_*H_];
__device__ __nv_bfloat16 g_Wo_hi [L_*H_*H_],   g_Wo_lo [L_*H_*H_];
__device__ __nv_bfloat16 g_Wgu_hi[L_*2*H_*F_], g_Wgu_lo[L_*2*H_*F_];
__device__ __nv_bfloat16 g_Wd_hi [L_*F_*H_],   g_Wd_lo [L_*F_*H_];

// ---------------- helpers ----------------
__device__ __forceinline__ uint32_t s2u(const void* p) {
    uint32_t a;
    asm("{ .reg .u64 t; cvta.to.shared.u64 t, %1; cvt.u32.u64 %0, t; }" : "=r"(a) : "l"(p));
    return a;
}
__device__ __forceinline__ void bsplit(float v, __nv_bfloat16& h, __nv_bfloat16& l) {
    h = __float2bfloat16(v);
    l = __float2bfloat16(v - __bfloat162float(h));
}
__device__ __forceinline__ void cpa16(uint32_t s, const void* g) {
    asm volatile("cp.async.ca.shared.global [%0], [%1], 16;" :: "r"(s), "l"(g) : "memory");
}
__device__ __forceinline__ void cp_commit() {
    asm volatile("cp.async.commit_group;" ::: "memory");
}
template<int NN> __device__ __forceinline__ void cp_wait() {
    asm volatile("cp.async.wait_group %0;" :: "n"(NN) : "memory");
}
__device__ __forceinline__ void mma16816(float* c, const uint32_t* a, const uint32_t* b) {
    asm volatile("mma.sync.aligned.m16n8k16.row.col.f32.bf16.bf16.f32 "
        "{%0,%1,%2,%3}, {%4,%5,%6,%7}, {%8,%9}, {%0,%1,%2,%3};"
        : "+f"(c[0]), "+f"(c[1]), "+f"(c[2]), "+f"(c[3])
        : "r"(a[0]), "r"(a[1]), "r"(a[2]), "r"(a[3]), "r"(b[0]), "r"(b[1]));
}
__device__ __forceinline__ void ldm_x4(uint32_t* r, uint32_t addr) {
    asm volatile("ldmatrix.sync.aligned.m8n8.x4.shared.b16 {%0,%1,%2,%3}, [%4];"
        : "=r"(r[0]), "=r"(r[1]), "=r"(r[2]), "=r"(r[3]) : "r"(addr));
}

// ============ bf16x3 tensor-core GEMM: C[M,N] (+)= A @ B^T ============
// A (act): [M,K] bf16 hi/lo row-major.  B (weightT): [N,K] bf16 hi/lo row-major.
// CTA 128x128, BK=32, 256 thr / 8 warps (2Mx4N), warp tile 64x32.
// smem: per stage 4 operand tiles of [128 rows][4 chunks of 16B], swizzled
//   chunk_sw = kc ^ ((row>>1)&3); tile = 8192 B; stage = 32768 B; 3 stages.
#define OPT_B   8192u
#define STAGE_B 32768u
#define NSTG    3
#define GSMEM_BYTES (NSTG*STAGE_B)   // 98304

template<bool ADD>
__global__ void __launch_bounds__(256)
gemm_bf16x3(const __nv_bfloat16* __restrict__ Ahi, const __nv_bfloat16* __restrict__ Alo,
            const __nv_bfloat16* __restrict__ Bhi, const __nv_bfloat16* __restrict__ Blo,
            float* __restrict__ C, int N, int K, size_t strideB, size_t strideC)
{
    extern __shared__ uint32_t smu[];
    Bhi += (size_t)blockIdx.z * strideB;
    Blo += (size_t)blockIdx.z * strideB;
    C   += (size_t)blockIdx.z * strideC;

    const int tid  = threadIdx.x;
    const int lane = tid & 31;
    const int wid  = tid >> 5;
    const int g    = lane >> 2;
    const int tg   = lane & 3;
    const int rbase = (wid & 1) * 64;
    const int cbase = (wid >> 1) * 32;
    const int row0 = blockIdx.y * 128;
    const int col0 = blockIdx.x * 128;

    const uint32_t smb = s2u(smu);

    // cp.async thread mapping: t -> (m = t>>2 [+64], kc = t&3)
    const int ld_m  = tid >> 2;
    const int ld_kc = tid & 3;

    auto load_stage = [&](int st, int ch) {
        const uint32_t base = smb + (uint32_t)st * STAGE_B;
        #pragma unroll
        for (int u = 0; u < 2; u++) {
            const int m = ld_m + u * 64;
            const uint32_t sw = (uint32_t)((m * 4 + (ld_kc ^ ((m >> 1) & 3))) << 4);
            const size_t ga = (size_t)(row0 + m) * K + ch * 32 + ld_kc * 8;
            const size_t gb = (size_t)(col0 + m) * K + ch * 32 + ld_kc * 8;
            cpa16(base +            sw, Ahi + ga);
            cpa16(base + OPT_B    + sw, Alo + ga);
            cpa16(base + 2*OPT_B  + sw, Bhi + gb);
            cpa16(base + 3*OPT_B  + sw, Blo + gb);
        }
        cp_commit();
    };

    // ldmatrix per-lane geometry
    const int li = lane & 7;
    const uint32_t aRowBase = (uint32_t)(rbase + li + ((lane >> 3) & 1) * 8);
    const uint32_t aKcSel   = (uint32_t)(lane >> 4);
    const uint32_t aXor     = (aRowBase >> 1) & 3u;
    const uint32_t bN0      = (uint32_t)(cbase + li + ((lane >> 4) << 3));
    const uint32_t bKcSel   = (uint32_t)((lane >> 3) & 1);
    const uint32_t bXor     = (bN0 >> 1) & 3u;

    float acc[4][4][4];
    #pragma unroll
    for (int mt = 0; mt < 4; mt++)
        #pragma unroll
        for (int nt = 0; nt < 4; nt++)
            #pragma unroll
            for (int c = 0; c < 4; c++) acc[mt][nt][c] = 0.f;

    const int nch = K / 32;
    load_stage(0, 0);
    load_stage(1, 1);

    for (int ch = 0; ch < nch; ch++) {
        const int st = ch % NSTG;
        if (ch < nch - 1) cp_wait<1>();
        else              cp_wait<0>();
        __syncthreads();
        if (ch + 2 < nch) load_stage((ch + 2) % NSTG, ch + 2);

        const uint32_t sbase = smb + (uint32_t)st * STAGE_B;
        #pragma unroll
        for (int ks = 0; ks < 2; ks++) {
            uint32_t bh[4][2], bl[4][2];
            {
                const uint32_t bkc = (uint32_t)(ks * 2) + bKcSel;
                const uint32_t a0 = sbase + 2*OPT_B + ((bN0 * 4u + (bkc ^ bXor)) << 4);
                uint32_t r[4];
                ldm_x4(r, a0);
                bh[0][0]=r[0]; bh[0][1]=r[1]; bh[1][0]=r[2]; bh[1][1]=r[3];
                ldm_x4(r, a0 + OPT_B);
                bl[0][0]=r[0]; bl[0][1]=r[1]; bl[1][0]=r[2]; bl[1][1]=r[3];
                ldm_x4(r, a0 + 1024u);                 // n + 16 rows
                bh[2][0]=r[0]; bh[2][1]=r[1]; bh[3][0]=r[2]; bh[3][1]=r[3];
                ldm_x4(r, a0 + OPT_B + 1024u);
                bl[2][0]=r[0]; bl[2][1]=r[1]; bl[3][0]=r[2]; bl[3][1]=r[3];
            }
            #pragma unroll
            for (int mt = 0; mt < 4; mt++) {
                const uint32_t arow = aRowBase + (uint32_t)(mt * 16);
                const uint32_t akc  = (uint32_t)(ks * 2) + aKcSel;
                const uint32_t aH = sbase + ((arow * 4u + (akc ^ aXor)) << 4);
                uint32_t ah[4], al[4];
                ldm_x4(ah, aH);
                ldm_x4(al, aH + OPT_B);
                #pragma unroll
                for (int nt = 0; nt < 4; nt++) {
                    mma16816(acc[mt][nt], ah, bh[nt]);
                    mma16816(acc[mt][nt], ah, bl[nt]);
                    mma16816(acc[mt][nt], al, bh[nt]);
                }
            }
        }
        __syncthreads();
    }

    // epilogue: c0,c1 -> (row, col..col+1); c2,c3 -> (row+8, ...)
    #pragma unroll
    for (int mt = 0; mt < 4; mt++) {
        #pragma unroll
        for (int nt = 0; nt < 4; nt++) {
            const int row = row0 + rbase + mt * 16 + g;
            const int col = col0 + cbase + nt * 8 + 2 * tg;
            float2 v0 = make_float2(acc[mt][nt][0], acc[mt][nt][1]);
            float2 v1 = make_float2(acc[mt][nt][2], acc[mt][nt][3]);
            float* p0 = C + (size_t)row * N + col;
            float* p1 = C + (size_t)(row + 8) * N + col;
            if (ADD) {
                float2 o0 = *(const float2*)p0;
                float2 o1 = *(const float2*)p1;
                v0.x += o0.x; v0.y += o0.y;
                v1.x += o1.x; v1.y += o1.y;
            }
            *(float2*)p0 = v0;
            *(float2*)p1 = v1;
        }
    }
}

// ---------------- LoRA fold: WeffT[n][k] (bf16 hi/lo) ----------------
__global__ void fold_kernel(const float* __restrict__ W, const float* __restrict__ A,
                            const float* __restrict__ Bm,
                            __nv_bfloat16* __restrict__ Whi, __nv_bfloat16* __restrict__ Wlo,
                            int KK, int N) {
    const int mat = blockIdx.z;
    const int i0 = blockIdx.x * 32, j0 = blockIdx.y * 32;
    W   += (size_t)mat * KK * N;
    A   += (size_t)mat * R_ * KK;
    Bm  += (size_t)mat * N * R_;
    Whi += (size_t)mat * (size_t)KK * N;
    Wlo += (size_t)mat * (size_t)KK * N;

    __shared__ float Wt[32][33];
    __shared__ float As[R_][33];
    __shared__ float Bs[32][R_+1];
    const int tx = threadIdx.x & 31, ty = threadIdx.x >> 5;   // 32 x 8
    #pragma unroll
    for (int u = 0; u < 4; u++) {
        int ii = ty * 4 + u;
        Wt[ii][tx] = W[(size_t)(i0 + ii) * N + j0 + tx];
    }
    #pragma unroll
    for (int u = 0; u < 2; u++) {
        int id = threadIdx.x + u * 256;
        As[id >> 5][id & 31] = A[(size_t)(id >> 5) * KK + i0 + (id & 31)];
    }
    #pragma unroll
    for (int u = 0; u < 2; u++) {
        int id = threadIdx.x + u * 256;
        Bs[id >> 4][id & 15] = Bm[(size_t)(j0 + (id >> 4)) * R_ + (id & 15)];
    }
    __syncthreads();
    #pragma unroll
    for (int u = 0; u < 4; u++) {
        int jj = ty * 4 + u;
        float s = 0.f;
        #pragma unroll
        for (int r = 0; r < R_; r++) s += As[r][tx] * Bs[jj][r];
        float v = Wt[tx][jj] + 2.0f * s;
        __nv_bfloat16 h, l; bsplit(v, h, l);
        size_t off = (size_t)(j0 + jj) * KK + i0 + tx;
        Whi[off] = h; Wlo[off] = l;
    }
}

// ---------------- h = x @ state_W + state_b ----------------
__global__ void init_h_kernel(const float* __restrict__ x, const float* __restrict__ W,
                              const float* __restrict__ b) {
    const int m = blockIdx.y;
    const int j = blockIdx.x*256 + threadIdx.x;
    __shared__ float xs[NT_];
    if (threadIdx.x < NT_) xs[threadIdx.x] = x[(size_t)m*NT_ + threadIdx.x];
    __syncthreads();
    float s = b[j];
    #pragma unroll
    for (int k = 0; k < NT_; k++) s += xs[k]*W[(size_t)k*H_ + j];
    g_h[(size_t)m*H_ + j] = s;
}

// ---------------- RMSNorm (fp32 out + bf16 hi/lo out) ----------------
__global__ void rms_kernel(const float* __restrict__ in, const float* __restrict__ w,
                           float* __restrict__ out,
                           __nv_bfloat16* __restrict__ ohi, __nv_bfloat16* __restrict__ olo) {
    const int m = blockIdx.x;
    const float* row = in + (size_t)m*H_;
    float s = 0.f;
    for (int i = threadIdx.x; i < H_; i += 256) { float v = row[i]; s += v*v; }
    __shared__ float red[8];
    #pragma unroll
    for (int o = 16; o; o >>= 1) s += __shfl_xor_sync(0xffffffffu, s, o);
    if ((threadIdx.x & 31) == 0) red[threadIdx.x >> 5] = s;
    __syncthreads();
    if (threadIdx.x < 8) {
        float v = red[threadIdx.x];
        #pragma unroll
        for (int o = 4; o; o >>= 1) v += __shfl_xor_sync(0xffu, v, o);
        if (threadIdx.x == 0) red[0] = v;
    }
    __syncthreads();
    const float inv = rsqrtf(red[0]*(1.0f/H_) + 1e-6f);
    for (int i = threadIdx.x; i < H_; i += 256) {
        float v = row[i]*inv*w[i];
        out[(size_t)m*H_ + i] = v;
        __nv_bfloat16 h, l; bsplit(v, h, l);
        ohi[(size_t)m*H_ + i] = h;
        olo[(size_t)m*H_ + i] = l;
    }
}

// ---------------- RoPE (in place, q & k via blockIdx.y) ----------------
__global__ void rope_kernel(float* __restrict__ qkv) {
    const int idx = blockIdx.x*256 + threadIdx.x;
    if (idx >= M_*NH_*32) return;
    const int i  = idx & 31;
    const int nh = (idx >> 5) & 15;
    const int m  = idx >> 9;
    const int t  = m & (T_-1);
    float* base = qkv + (size_t)blockIdx.y*MH_ + (size_t)m*H_ + nh*HD_;
    const float x1 = base[i], x2 = base[i+32];
    const float inv = expf(-(float)i * (1.0f/32.0f) * 9.210340371976184f);
    const float ang = (float)t * inv;
    const float c = cosf(ang), sn = sinf(ang);
    base[i]    = x1*c - x2*sn;
    base[i+32] = x2*c + x1*sn;
}

// ---------------- flash attention (fp32, causal) -> bf16 hi/lo out ----------------
#define AQ 64
#define AK 32
__global__ void attn_kernel(const float* __restrict__ qkv,
                            __nv_bfloat16* __restrict__ att_hi,
                            __nv_bfloat16* __restrict__ att_lo) {
    const int qt = blockIdx.x, nh = blockIdx.y, b = blockIdx.z;
    const int tid = threadIdx.x;
    const int tx = tid & 15;
    const int ty = tid >> 4;
    __shared__ __align__(16) float Qs[AQ][HD_+4];
    __shared__ __align__(16) float Ks[AK][HD_+4];
    __shared__ __align__(16) float Vs[AK][HD_+4];
    __shared__ __align__(16) float Ps[AQ][AK+4];
    const size_t baseQ  = (size_t)(b*T_ + qt*AQ)*H_ + nh*HD_;
    const size_t baseKV = (size_t)(b*T_)*H_ + nh*HD_;
    const float* Qg = qkv + baseQ;
    const float* Kg = qkv + MH_   + baseKV;
    const float* Vg = qkv + 2*MH_ + baseKV;
    #pragma unroll
    for (int u = 0; u < 4; u++) {
        int q = tid + u*256;
        int r = q >> 4, c = (q & 15) << 2;
        *(float4*)(&Qs[r][c]) = *(const float4*)(Qg + (size_t)r*H_ + c);
    }
    float m_i[4], l_i[4], O[4][4];
    #pragma unroll
    for (int i = 0; i < 4; i++) {
        m_i[i] = -1e30f; l_i[i] = 0.f;
        #pragma unroll
        for (int j = 0; j < 4; j++) O[i][j] = 0.f;
    }
    const int nkv = 2*qt + 2;
    for (int kvt = 0; kvt < nkv; kvt++) {
        __syncthreads();
        #pragma unroll
        for (int u = 0; u < 2; u++) {
            int q = tid + u*256;
            int r = q >> 4, c = (q & 15) << 2;
            *(float4*)(&Ks[r][c]) = *(const float4*)(Kg + (size_t)(kvt*AK + r)*H_ + c);
            *(float4*)(&Vs[r][c]) = *(const float4*)(Vg + (size_t)(kvt*AK + r)*H_ + c);
        }
        __syncthreads();
        float s[4][2] = {};
        #pragma unroll
        for (int k4 = 0; k4 < HD_; k4 += 4) {
            float4 q0 = *(const float4*)&Qs[ty*4+0][k4];
            float4 q1 = *(const float4*)&Qs[ty*4+1][k4];
            float4 q2 = *(const float4*)&Qs[ty*4+2][k4];
            float4 q3 = *(const float4*)&Qs[ty*4+3][k4];
            float4 ka = *(const float4*)&Ks[tx*2+0][k4];
            float4 kb = *(const float4*)&Ks[tx*2+1][k4];
            s[0][0] += q0.x*ka.x + q0.y*ka.y + q0.z*ka.z + q0.w*ka.w;
            s[0][1] += q0.x*kb.x + q0.y*kb.y + q0.z*kb.z + q0.w*kb.w;
            s[1][0] += q1.x*ka.x + q1.y*ka.y + q1.z*ka.z + q1.w*ka.w;
            s[1][1] += q1.x*kb.x + q1.y*kb.y + q1.z*kb.z + q1.w*kb.w;
            s[2][0] += q2.x*ka.x + q2.y*ka.y + q2.z*ka.z + q2.w*ka.w;
            s[2][1] += q2.x*kb.x + q2.y*kb.y + q2.z*kb.z + q2.w*kb.w;
            s[3][0] += q3.x*ka.x + q3.y*ka.y + q3.z*ka.z + q3.w*ka.w;
            s[3][1] += q3.x*kb.x + q3.y*kb.y + q3.z*kb.z + q3.w*kb.w;
        }
        #pragma unroll
        for (int i = 0; i < 4; i++) {
            const int qrow = qt*AQ + ty*4 + i;
            #pragma unroll
            for (int j = 0; j < 2; j++) {
                const int kcol = kvt*AK + tx*2 + j;
                s[i][j] = (kcol <= qrow) ? s[i][j]*0.125f : -1e9f;
            }
        }
        #pragma unroll
        for (int i = 0; i < 4; i++) {
            float mx = fmaxf(s[i][0], s[i][1]);
            #pragma unroll
            for (int o = 8; o; o >>= 1) mx = fmaxf(mx, __shfl_xor_sync(0xffffffffu, mx, o));
            const float mn = fmaxf(m_i[i], mx);
            const float p0 = expf(s[i][0]-mn), p1 = expf(s[i][1]-mn);
            float rs = p0 + p1;
            #pragma unroll
            for (int o = 8; o; o >>= 1) rs += __shfl_xor_sync(0xffffffffu, rs, o);
            const float alpha = expf(m_i[i]-mn);
            m_i[i] = mn;
            l_i[i] = l_i[i]*alpha + rs;
            #pragma unroll
            for (int j = 0; j < 4; j++) O[i][j] *= alpha;
            Ps[ty*4+i][tx*2+0] = p0;
            Ps[ty*4+i][tx*2+1] = p1;
        }
        __syncthreads();
        #pragma unroll
        for (int k4 = 0; k4 < AK; k4 += 4) {
            float4 v0 = *(const float4*)&Vs[k4+0][tx*4];
            float4 v1 = *(const float4*)&Vs[k4+1][tx*4];
            float4 v2 = *(const float4*)&Vs[k4+2][tx*4];
            float4 v3 = *(const float4*)&Vs[k4+3][tx*4];
            #pragma unroll
            for (int i = 0; i < 4; i++) {
                float4 p = *(const float4*)&Ps[ty*4+i][k4];
                O[i][0] += p.x*v0.x + p.y*v1.x + p.z*v2.x + p.w*v3.x;
                O[i][1] += p.x*v0.y + p.y*v1.y + p.z*v2.y + p.w*v3.y;
                O[i][2] += p.x*v0.z + p.y*v1.z + p.z*v2.z + p.w*v3.z;
                O[i][3] += p.x*v0.w + p.y*v1.w + p.z*v2.w + p.w*v3.w;
            }
        }
    }
    #pragma unroll
    for (int i = 0; i < 4; i++) {
        const float invl = 1.0f/l_i[i];
        const size_t off = (size_t)(b*T_ + qt*AQ + ty*4 + i)*H_ + nh*HD_ + tx*4;
        #pragma unroll
        for (int j = 0; j < 4; j++) {
            float v = O[i][j]*invl;
            __nv_bfloat16 h, l; bsplit(v, h, l);
            att_hi[off + j] = h;
            att_lo[off + j] = l;
        }
    }
}

// ---------------- SwiGLU: act = silu(g) * u -> bf16 hi/lo ----------------
__global__ void silu_kernel(const float* __restrict__ g, const float* __restrict__ u,
                            __nv_bfloat16* __restrict__ ahi, __nv_bfloat16* __restrict__ alo,
                            int n) {
    const int i = blockIdx.x*256 + threadIdx.x;
    if (i < n) {
        const float gv = g[i];
        float v = (gv / (1.0f + expf(-gv))) * u[i];
        __nv_bfloat16 h, l; bsplit(v, h, l);
        ahi[i] = h; alo[i] = l;
    }
}

// ---------------- head: logits = latent@W + b, clamp, softmax ----------------
__global__ void head_kernel(const float* __restrict__ latent, const float* __restrict__ W,
                            const float* __restrict__ bias, const float* __restrict__ temp,
                            float* __restrict__ out) {
    const int m = blockIdx.x;
    __shared__ float xs[H_];
    __shared__ float red[8][32];
    const float* row = latent + (size_t)m*H_;
    for (int i = threadIdx.x; i < H_; i += 256) xs[i] = row[i];
    __syncthreads();
    const int n  = threadIdx.x & 31;
    const int ch = threadIdx.x >> 5;
    float p = 0.f;
    if (n < 31) {
        const int k0 = ch*128;
        for (int k = k0; k < k0 + 128; k++) p += xs[k]*W[(size_t)k*31 + n];
    }
    red[ch][n] = p;
    __syncthreads();
    if (threadIdx.x < 32) {
        float v = 0.f;
        if (n < 31) {
            #pragma unroll
            for (int c = 0; c < 8; c++) v += red[c][n];
            v += bias[n];
            v = fminf(fmaxf(v, -10.0f), 10.0f);
            out[(size_t)M_*31 + (size_t)m*31 + n] = v;
        }
        const float t = *temp;
        float mx = (n < 31) ? v : -1e30f;
        #pragma unroll
        for (int o = 16; o; o >>= 1) mx = fmaxf(mx, __shfl_xor_sync(0xffffffffu, mx, o));
        const float ev = (n < 31) ? expf((v - mx)/t) : 0.f;
        float sm = ev;
        #pragma unroll
        for (int o = 16; o; o >>= 1) sm += __shfl_xor_sync(0xffffffffu, sm, o);
        if (n < 31) out[(size_t)m*31 + n] = ev/sm;
    }
}

// ---------------- launcher ----------------
extern "C" void kernel_launch(void* const* d_in, const int* in_sizes, int n_in,
                              void* d_out, int out_size) {
    (void)in_sizes; (void)n_in; (void)out_size;
    const float* x       = (const float*)d_in[0];
    const float* temp    = (const float*)d_in[1];
    const float* state_W = (const float*)d_in[2];
    const float* state_b = (const float*)d_in[3];
    const float* ln1     = (const float*)d_in[4];
    const float* ln2     = (const float*)d_in[5];
    const float* Wqkv    = (const float*)d_in[6];
    const float* Aqkv    = (const float*)d_in[7];
    const float* Bqkv    = (const float*)d_in[8];
    const float* Wo      = (const float*)d_in[9];
    const float* Ao      = (const float*)d_in[10];
    const float* Bo      = (const float*)d_in[11];
    const float* Wgu     = (const float*)d_in[12];
    const float* Agu     = (const float*)d_in[13];
    const float* Bgu     = (const float*)d_in[14];
    const float* Wd      = (const float*)d_in[15];
    const float* Ad      = (const float*)d_in[16];
    const float* Bd      = (const float*)d_in[17];
    const float* ln_f    = (const float*)d_in[18];
    const float* head_W  = (const float*)d_in[19];
    const float* head_b  = (const float*)d_in[20];
    float* out = (float*)d_out;

    float *p_h, *p_hn, *p_qkv, *p_gu;
    __nv_bfloat16 *p_hn_hi, *p_hn_lo, *p_att_hi, *p_att_lo, *p_act_hi, *p_act_lo;
    __nv_bfloat16 *pWq_hi, *pWq_lo, *pWo_hi, *pWo_lo, *pWgu_hi, *pWgu_lo, *pWd_hi, *pWd_lo;
    cudaGetSymbolAddress((void**)&p_h,     g_h);
    cudaGetSymbolAddress((void**)&p_hn,    g_hn);
    cudaGetSymbolAddress((void**)&p_qkv,   g_qkv);
    cudaGetSymbolAddress((void**)&p_gu,    g_gu);
    cudaGetSymbolAddress((void**)&p_hn_hi, g_hn_hi);
    cudaGetSymbolAddress((void**)&p_hn_lo, g_hn_lo);
    cudaGetSymbolAddress((void**)&p_att_hi,g_att_hi);
    cudaGetSymbolAddress((void**)&p_att_lo,g_att_lo);
    cudaGetSymbolAddress((void**)&p_act_hi,g_act_hi);
    cudaGetSymbolAddress((void**)&p_act_lo,g_act_lo);
    cudaGetSymbolAddress((void**)&pWq_hi,  g_Wq_hi);
    cudaGetSymbolAddress((void**)&pWq_lo,  g_Wq_lo);
    cudaGetSymbolAddress((void**)&pWo_hi,  g_Wo_hi);
    cudaGetSymbolAddress((void**)&pWo_lo,  g_Wo_lo);
    cudaGetSymbolAddress((void**)&pWgu_hi, g_Wgu_hi);
    cudaGetSymbolAddress((void**)&pWgu_lo, g_Wgu_lo);
    cudaGetSymbolAddress((void**)&pWd_hi,  g_Wd_hi);
    cudaGetSymbolAddress((void**)&pWd_lo,  g_Wd_lo);

    cudaFuncSetAttribute(gemm_bf16x3<false>, cudaFuncAttributeMaxDynamicSharedMemorySize, GSMEM_BYTES);
    cudaFuncSetAttribute(gemm_bf16x3<true>,  cudaFuncAttributeMaxDynamicSharedMemorySize, GSMEM_BYTES);

    // ---- fold LoRA + transpose + bf16-split effective weights ----
    fold_kernel<<<dim3(32, 32, 24), 256>>>(Wqkv, Aqkv, Bqkv, pWq_hi,  pWq_lo,  H_, H_);
    fold_kernel<<<dim3(32, 32,  8), 256>>>(Wo,   Ao,   Bo,   pWo_hi,  pWo_lo,  H_, H_);
    fold_kernel<<<dim3(32, 88, 16), 256>>>(Wgu,  Agu,  Bgu,  pWgu_hi, pWgu_lo, H_, F_);
    fold_kernel<<<dim3(88, 32,  8), 256>>>(Wd,   Ad,   Bd,   pWd_hi,  pWd_lo,  F_, H_);

    // ---- embed ----
    init_h_kernel<<<dim3(4, M_), 256>>>(x, state_W, state_b);

    // ---- layers ----
    for (int l = 0; l < L_; l++) {
        rms_kernel<<<M_, 256>>>(p_h, ln1 + (size_t)l*H_, p_hn, p_hn_hi, p_hn_lo);
        gemm_bf16x3<false><<<dim3(8, 16, 3), 256, GSMEM_BYTES>>>(
            p_hn_hi, p_hn_lo, pWq_hi + (size_t)l*3*HH_, pWq_lo + (size_t)l*3*HH_,
            p_qkv, H_, H_, HH_, MH_);
        rope_kernel<<<dim3(4096, 2), 256>>>(p_qkv);
        attn_kernel<<<dim3(16, 16, 2), 256>>>(p_qkv, p_att_hi, p_att_lo);
        gemm_bf16x3<true><<<dim3(8, 16, 1), 256, GSMEM_BYTES>>>(
            p_att_hi, p_att_lo, pWo_hi + (size_t)l*HH_, pWo_lo + (size_t)l*HH_,
            p_h, H_, H_, 0, 0);
        rms_kernel<<<M_, 256>>>(p_h, ln2 + (size_t)l*H_, p_hn, p_hn_hi, p_hn_lo);
        gemm_bf16x3<false><<<dim3(22, 16, 2), 256, GSMEM_BYTES>>>(
            p_hn_hi, p_hn_lo, pWgu_hi + (size_t)l*2*HF_, pWgu_lo + (size_t)l*2*HF_,
            p_gu, F_, H_, HF_, MF_);
        silu_kernel<<<(int)((MF_ + 255)/256), 256>>>(p_gu, p_gu + MF_, p_act_hi, p_act_lo, (int)MF_);
        gemm_bf16x3<true><<<dim3(8, 16, 1), 256, GSMEM_BYTES>>>(
            p_act_hi, p_act_lo, pWd_hi + (size_t)l*HF_, pWd_lo + (size_t)l*HF_,
            p_h, H_, F_, 0, 0);
    }

    // ---- final norm + head + softmax ----
    rms_kernel<<<M_, 256>>>(p_h, ln_f, p_hn, p_hn_hi, p_hn_lo);
    head_kernel<<<M_, 256>>>(p_hn, head_W, head_b, temp, out);
}

// round 14
// speedup vs baseline: 2.4952x; 1.0617x over previous
#include <cuda_runtime.h>
#include <cuda_bf16.h>
#include <math.h>
#include <stdint.h>

// ---------------- problem constants ----------------
#define B_   2
#define T_   1024
#define NT_  30
#define H_   1024
#define L_   8
#define F_   2816
#define NH_  16
#define HD_  64
#define R_   16
#define M_   (B_*T_)                 // 2048 tokens
#define MH_  ((size_t)M_*H_)
#define HH_  ((size_t)H_*H_)
#define HF_  ((size_t)H_*F_)
#define MF_  ((size_t)M_*F_)

// ---------------- scratch (device globals: no allocation allowed) ----------------
__device__ float g_h  [M_*H_];       // fp32 residual stream
__device__ float g_hn [M_*H_];       // fp32 rms out (head input)
__device__ float g_qkv[3*M_*H_];     // qkv; later Wo split-K partials (2*MH)
__device__ float g_gu [2*M_*F_];     // gu;  later Wd split-K partials (2*MH)
// bf16 hi/lo activation operands
__device__ __nv_bfloat16 g_hn_hi [M_*H_], g_hn_lo [M_*H_];
__device__ __nv_bfloat16 g_att_hi[M_*H_], g_att_lo[M_*H_];
__device__ __nv_bfloat16 g_act_hi[M_*F_], g_act_lo[M_*F_];
// fused+TRANSPOSED effective weights as bf16 hi/lo: W_T[n][k]
__device__ __nv_bfloat16 g_Wq_hi [L_*3*H_*H_], g_Wq_lo [L_*3*H_*H_];
__device__ __nv_bfloat16 g_Wo_hi [L_*H_*H_],   g_Wo_lo [L_*H_*H_];
__device__ __nv_bfloat16 g_Wgu_hi[L_*2*H_*F_], g_Wgu_lo[L_*2*H_*F_];
__device__ __nv_bfloat16 g_Wd_hi [L_*F_*H_],   g_Wd_lo [L_*F_*H_];

// ---------------- helpers ----------------
__device__ __forceinline__ uint32_t s2u(const void* p) {
    uint32_t a;
    asm("{ .reg .u64 t; cvta.to.shared.u64 t, %1; cvt.u32.u64 %0, t; }" : "=r"(a) : "l"(p));
    return a;
}
__device__ __forceinline__ void bsplit(float v, __nv_bfloat16& h, __nv_bfloat16& l) {
    h = __float2bfloat16(v);
    l = __float2bfloat16(v - __bfloat162float(h));
}
__device__ __forceinline__ void cpa16(uint32_t s, const void* g) {
    asm volatile("cp.async.ca.shared.global [%0], [%1], 16;" :: "r"(s), "l"(g) : "memory");
}
__device__ __forceinline__ void cp_commit() {
    asm volatile("cp.async.commit_group;" ::: "memory");
}
template<int NN> __device__ __forceinline__ void cp_wait() {
    asm volatile("cp.async.wait_group %0;" :: "n"(NN) : "memory");
}
__device__ __forceinline__ void mma16816(float* c, const uint32_t* a, const uint32_t* b) {
    asm volatile("mma.sync.aligned.m16n8k16.row.col.f32.bf16.bf16.f32 "
        "{%0,%1,%2,%3}, {%4,%5,%6,%7}, {%8,%9}, {%0,%1,%2,%3};"
        : "+f"(c[0]), "+f"(c[1]), "+f"(c[2]), "+f"(c[3])
        : "r"(a[0]), "r"(a[1]), "r"(a[2]), "r"(a[3]), "r"(b[0]), "r"(b[1]));
}
__device__ __forceinline__ void ldm_x4(uint32_t* r, uint32_t addr) {
    asm volatile("ldmatrix.sync.aligned.m8n8.x4.shared.b16 {%0,%1,%2,%3}, [%4];"
        : "=r"(r[0]), "=r"(r[1]), "=r"(r[2]), "=r"(r[3]) : "r"(addr));
}

// ============ bf16x3 tensor-core GEMM: C[M,N] = A @ B^T (slice of K) ============
// A: [M,lda] bf16 hi/lo row-major; B: [N,lda] bf16 hi/lo row-major.
// Per-z: B += z*strideB, C += z*strideC, k-window start = z*kOffPerZ, length Klen.
// CTA 128x128, 128 threads / 4 warps (2Mx2N), warp tile 64x64, BK=32, 3 stages.
#define OPT_B   8192u
#define STAGE_B 32768u
#define NSTG    3
#define GSMEM_BYTES (NSTG*STAGE_B)   // 98304

__global__ void __launch_bounds__(128)
gemm_bf16x3(const __nv_bfloat16* __restrict__ Ahi, const __nv_bfloat16* __restrict__ Alo,
            const __nv_bfloat16* __restrict__ Bhi, const __nv_bfloat16* __restrict__ Blo,
            float* __restrict__ C, int N, int Klen, int lda,
            size_t strideB, size_t strideC, int kOffPerZ)
{
    extern __shared__ uint32_t smu[];
    const int kOff = (int)blockIdx.z * kOffPerZ;
    Bhi += (size_t)blockIdx.z * strideB;
    Blo += (size_t)blockIdx.z * strideB;
    C   += (size_t)blockIdx.z * strideC;

    const int tid  = threadIdx.x;
    const int lane = tid & 31;
    const int wid  = tid >> 5;
    const int g    = lane >> 2;
    const int tg   = lane & 3;
    const int rbase = (wid & 1) * 64;
    const int cbase = (wid >> 1) * 64;
    const int row0 = blockIdx.y * 128;
    const int col0 = blockIdx.x * 128;

    const uint32_t smb = s2u(smu);

    // cp.async mapping: 128 threads -> (m = tid>>2 [+32*u], kc = tid&3)
    const int ld_m  = tid >> 2;      // 0..31
    const int ld_kc = tid & 3;

    auto load_stage = [&](int st, int ch) {
        const uint32_t base = smb + (uint32_t)st * STAGE_B;
        #pragma unroll
        for (int u = 0; u < 4; u++) {
            const int m = ld_m + u * 32;
            const uint32_t sw = (uint32_t)((m * 4 + (ld_kc ^ ((m >> 1) & 3))) << 4);
            const size_t ga = (size_t)(row0 + m) * lda + kOff + ch * 32 + ld_kc * 8;
            const size_t gb = (size_t)(col0 + m) * lda + kOff + ch * 32 + ld_kc * 8;
            cpa16(base +            sw, Ahi + ga);
            cpa16(base + OPT_B    + sw, Alo + ga);
            cpa16(base + 2*OPT_B  + sw, Bhi + gb);
            cpa16(base + 3*OPT_B  + sw, Blo + gb);
        }
        cp_commit();
    };

    // ldmatrix per-lane geometry
    const int li = lane & 7;
    const uint32_t aRowBase = (uint32_t)(rbase + li + ((lane >> 3) & 1) * 8);
    const uint32_t aKcSel   = (uint32_t)(lane >> 4);
    const uint32_t bN0      = (uint32_t)(cbase + li + ((lane >> 4) << 3));
    const uint32_t bKcSel   = (uint32_t)((lane >> 3) & 1);
    const uint32_t bXor     = (bN0 >> 1) & 3u;

    float acc[4][8][4];
    #pragma unroll
    for (int mt = 0; mt < 4; mt++)
        #pragma unroll
        for (int nt = 0; nt < 8; nt++)
            #pragma unroll
            for (int c = 0; c < 4; c++) acc[mt][nt][c] = 0.f;

    const int nch = Klen / 32;
    load_stage(0, 0);
    load_stage(1, 1);

    for (int ch = 0; ch < nch; ch++) {
        const int st = ch % NSTG;
        if (ch < nch - 1) cp_wait<1>();
        else              cp_wait<0>();
        __syncthreads();
        if (ch + 2 < nch) load_stage((ch + 2) % NSTG, ch + 2);

        const uint32_t sbase = smb + (uint32_t)st * STAGE_B;
        #pragma unroll
        for (int ks = 0; ks < 2; ks++) {
            uint32_t bh[8][2], bl[8][2];
            {
                const uint32_t bkc = (uint32_t)(ks * 2) + bKcSel;
                const uint32_t a0 = sbase + 2*OPT_B + ((bN0 * 4u + (bkc ^ bXor)) << 4);
                #pragma unroll
                for (int gg = 0; gg < 4; gg++) {            // n-tile pairs (16g, 16g+8)
                    uint32_t r[4];
                    ldm_x4(r, a0 + (uint32_t)(gg * 1024));
                    bh[gg*2+0][0]=r[0]; bh[gg*2+0][1]=r[1];
                    bh[gg*2+1][0]=r[2]; bh[gg*2+1][1]=r[3];
                    ldm_x4(r, a0 + OPT_B + (uint32_t)(gg * 1024));
                    bl[gg*2+0][0]=r[0]; bl[gg*2+0][1]=r[1];
                    bl[gg*2+1][0]=r[2]; bl[gg*2+1][1]=r[3];
                }
            }
            #pragma unroll
            for (int mt = 0; mt < 4; mt++) {
                const uint32_t arow = aRowBase + (uint32_t)(mt * 16);
                const uint32_t akc  = (uint32_t)(ks * 2) + aKcSel;
                const uint32_t aH = sbase + ((arow * 4u + (akc ^ ((arow >> 1) & 3u))) << 4);
                uint32_t ah[4], al[4];
                ldm_x4(ah, aH);
                ldm_x4(al, aH + OPT_B);
                #pragma unroll
                for (int nt = 0; nt < 8; nt++) {
                    mma16816(acc[mt][nt], ah, bh[nt]);
                    mma16816(acc[mt][nt], ah, bl[nt]);
                    mma16816(acc[mt][nt], al, bh[nt]);
                }
            }
        }
        __syncthreads();
    }

    // epilogue: plain store (residual handled downstream)
    #pragma unroll
    for (int mt = 0; mt < 4; mt++) {
        #pragma unroll
        for (int nt = 0; nt < 8; nt++) {
            const int row = row0 + rbase + mt * 16 + g;
            const int col = col0 + cbase + nt * 8 + 2 * tg;
            *(float2*)(C + (size_t)row * N + col)       = make_float2(acc[mt][nt][0], acc[mt][nt][1]);
            *(float2*)(C + (size_t)(row + 8) * N + col) = make_float2(acc[mt][nt][2], acc[mt][nt][3]);
        }
    }
}

// ---------------- LoRA fold: WeffT[n][k] (bf16 hi/lo) ----------------
__global__ void fold_kernel(const float* __restrict__ W, const float* __restrict__ A,
                            const float* __restrict__ Bm,
                            __nv_bfloat16* __restrict__ Whi, __nv_bfloat16* __restrict__ Wlo,
                            int KK, int N) {
    const int mat = blockIdx.z;
    const int i0 = blockIdx.x * 32, j0 = blockIdx.y * 32;
    W   += (size_t)mat * KK * N;
    A   += (size_t)mat * R_ * KK;
    Bm  += (size_t)mat * N * R_;
    Whi += (size_t)mat * (size_t)KK * N;
    Wlo += (size_t)mat * (size_t)KK * N;

    __shared__ float Wt[32][33];
    __shared__ float As[R_][33];
    __shared__ float Bs[32][R_+1];
    const int tx = threadIdx.x & 31, ty = threadIdx.x >> 5;   // 32 x 8
    #pragma unroll
    for (int u = 0; u < 4; u++) {
        int ii = ty * 4 + u;
        Wt[ii][tx] = W[(size_t)(i0 + ii) * N + j0 + tx];
    }
    #pragma unroll
    for (int u = 0; u < 2; u++) {
        int id = threadIdx.x + u * 256;
        As[id >> 5][id & 31] = A[(size_t)(id >> 5) * KK + i0 + (id & 31)];
    }
    #pragma unroll
    for (int u = 0; u < 2; u++) {
        int id = threadIdx.x + u * 256;
        Bs[id >> 4][id & 15] = Bm[(size_t)(j0 + (id >> 4)) * R_ + (id & 15)];
    }
    __syncthreads();
    #pragma unroll
    for (int u = 0; u < 4; u++) {
        int jj = ty * 4 + u;
        float s = 0.f;
        #pragma unroll
        for (int r = 0; r < R_; r++) s += As[r][tx] * Bs[jj][r];
        float v = Wt[tx][jj] + 2.0f * s;
        __nv_bfloat16 h, l; bsplit(v, h, l);
        size_t off = (size_t)(j0 + jj) * KK + i0 + tx;
        Whi[off] = h; Wlo[off] = l;
    }
}

// ---------------- h = x @ state_W + state_b ----------------
__global__ void init_h_kernel(const float* __restrict__ x, const float* __restrict__ W,
                              const float* __restrict__ b) {
    const int m = blockIdx.y;
    const int j = blockIdx.x*256 + threadIdx.x;
    __shared__ float xs[NT_];
    if (threadIdx.x < NT_) xs[threadIdx.x] = x[(size_t)m*NT_ + threadIdx.x];
    __syncthreads();
    float s = b[j];
    #pragma unroll
    for (int k = 0; k < NT_; k++) s += xs[k]*W[(size_t)k*H_ + j];
    g_h[(size_t)m*H_ + j] = s;
}

// ---------------- RMSNorm (plain) ----------------
__global__ void rms_kernel(const float* __restrict__ in, const float* __restrict__ w,
                           float* __restrict__ out,
                           __nv_bfloat16* __restrict__ ohi, __nv_bfloat16* __restrict__ olo) {
    const int m = blockIdx.x;
    const float* row = in + (size_t)m*H_;
    float s = 0.f;
    for (int i = threadIdx.x; i < H_; i += 256) { float v = row[i]; s += v*v; }
    __shared__ float red[8];
    #pragma unroll
    for (int o = 16; o; o >>= 1) s += __shfl_xor_sync(0xffffffffu, s, o);
    if ((threadIdx.x & 31) == 0) red[threadIdx.x >> 5] = s;
    __syncthreads();
    if (threadIdx.x < 8) {
        float v = red[threadIdx.x];
        #pragma unroll
        for (int o = 4; o; o >>= 1) v += __shfl_xor_sync(0xffu, v, o);
        if (threadIdx.x == 0) red[0] = v;
    }
    __syncthreads();
    const float inv = rsqrtf(red[0]*(1.0f/H_) + 1e-6f);
    for (int i = threadIdx.x; i < H_; i += 256) {
        float v = row[i]*inv*w[i];
        out[(size_t)m*H_ + i] = v;
        __nv_bfloat16 h, l; bsplit(v, h, l);
        ohi[(size_t)m*H_ + i] = h;
        olo[(size_t)m*H_ + i] = l;
    }
}

// ---------------- fused: h += P0 + P1; rms(h) ----------------
__global__ void rms3_kernel(float* __restrict__ hbuf,
                            const float* __restrict__ P0, const float* __restrict__ P1,
                            const float* __restrict__ w,
                            float* __restrict__ out,
                            __nv_bfloat16* __restrict__ ohi, __nv_bfloat16* __restrict__ olo) {
    const int m = blockIdx.x;
    const size_t base = (size_t)m * H_;
    float v4[4];
    float s = 0.f;
    #pragma unroll
    for (int u = 0; u < 4; u++) {
        const int i = threadIdx.x + u * 256;
        float v = hbuf[base + i] + P0[base + i] + P1[base + i];
        v4[u] = v;
        s += v * v;
        hbuf[base + i] = v;
    }
    __shared__ float red[8];
    #pragma unroll
    for (int o = 16; o; o >>= 1) s += __shfl_xor_sync(0xffffffffu, s, o);
    if ((threadIdx.x & 31) == 0) red[threadIdx.x >> 5] = s;
    __syncthreads();
    if (threadIdx.x < 8) {
        float v = red[threadIdx.x];
        #pragma unroll
        for (int o = 4; o; o >>= 1) v += __shfl_xor_sync(0xffu, v, o);
        if (threadIdx.x == 0) red[0] = v;
    }
    __syncthreads();
    const float inv = rsqrtf(red[0]*(1.0f/H_) + 1e-6f);
    #pragma unroll
    for (int u = 0; u < 4; u++) {
        const int i = threadIdx.x + u * 256;
        float v = v4[u] * inv * w[i];
        out[base + i] = v;
        __nv_bfloat16 h, l; bsplit(v, h, l);
        ohi[base + i] = h;
        olo[base + i] = l;
    }
}

// ---------------- RoPE (in place, q & k via blockIdx.y) ----------------
__global__ void rope_kernel(float* __restrict__ qkv) {
    const int idx = blockIdx.x*256 + threadIdx.x;
    if (idx >= M_*NH_*32) return;
    const int i  = idx & 31;
    const int nh = (idx >> 5) & 15;
    const int m  = idx >> 9;
    const int t  = m & (T_-1);
    float* base = qkv + (size_t)blockIdx.y*MH_ + (size_t)m*H_ + nh*HD_;
    const float x1 = base[i], x2 = base[i+32];
    const float inv = expf(-(float)i * (1.0f/32.0f) * 9.210340371976184f);
    const float ang = (float)t * inv;
    const float c = cosf(ang), sn = sinf(ang);
    base[i]    = x1*c - x2*sn;
    base[i+32] = x2*c + x1*sn;
}

// ---------------- flash attention (fp32, causal) -> bf16 hi/lo out ----------------
#define AQ 64
#define AK 32
__global__ void attn_kernel(const float* __restrict__ qkv,
                            __nv_bfloat16* __restrict__ att_hi,
                            __nv_bfloat16* __restrict__ att_lo) {
    const int qt = blockIdx.x, nh = blockIdx.y, b = blockIdx.z;
    const int tid = threadIdx.x;
    const int tx = tid & 15;
    const int ty = tid >> 4;
    __shared__ __align__(16) float Qs[AQ][HD_+4];
    __shared__ __align__(16) float Ks[AK][HD_+4];
    __shared__ __align__(16) float Vs[AK][HD_+4];
    __shared__ __align__(16) float Ps[AQ][AK+4];
    const size_t baseQ  = (size_t)(b*T_ + qt*AQ)*H_ + nh*HD_;
    const size_t baseKV = (size_t)(b*T_)*H_ + nh*HD_;
    const float* Qg = qkv + baseQ;
    const float* Kg = qkv + MH_   + baseKV;
    const float* Vg = qkv + 2*MH_ + baseKV;
    #pragma unroll
    for (int u = 0; u < 4; u++) {
        int q = tid + u*256;
        int r = q >> 4, c = (q & 15) << 2;
        *(float4*)(&Qs[r][c]) = *(const float4*)(Qg + (size_t)r*H_ + c);
    }
    float m_i[4], l_i[4], O[4][4];
    #pragma unroll
    for (int i = 0; i < 4; i++) {
        m_i[i] = -1e30f; l_i[i] = 0.f;
        #pragma unroll
        for (int j = 0; j < 4; j++) O[i][j] = 0.f;
    }
    const int nkv = 2*qt + 2;
    for (int kvt = 0; kvt < nkv; kvt++) {
        __syncthreads();
        #pragma unroll
        for (int u = 0; u < 2; u++) {
            int q = tid + u*256;
            int r = q >> 4, c = (q & 15) << 2;
            *(float4*)(&Ks[r][c]) = *(const float4*)(Kg + (size_t)(kvt*AK + r)*H_ + c);
            *(float4*)(&Vs[r][c]) = *(const float4*)(Vg + (size_t)(kvt*AK + r)*H_ + c);
        }
        __syncthreads();
        float s[4][2] = {};
        #pragma unroll
        for (int k4 = 0; k4 < HD_; k4 += 4) {
            float4 q0 = *(const float4*)&Qs[ty*4+0][k4];
            float4 q1 = *(const float4*)&Qs[ty*4+1][k4];
            float4 q2 = *(const float4*)&Qs[ty*4+2][k4];
            float4 q3 = *(const float4*)&Qs[ty*4+3][k4];
            float4 ka = *(const float4*)&Ks[tx*2+0][k4];
            float4 kb = *(const float4*)&Ks[tx*2+1][k4];
            s[0][0] += q0.x*ka.x + q0.y*ka.y + q0.z*ka.z + q0.w*ka.w;
            s[0][1] += q0.x*kb.x + q0.y*kb.y + q0.z*kb.z + q0.w*kb.w;
            s[1][0] += q1.x*ka.x + q1.y*ka.y + q1.z*ka.z + q1.w*ka.w;
            s[1][1] += q1.x*kb.x + q1.y*kb.y + q1.z*kb.z + q1.w*kb.w;
            s[2][0] += q2.x*ka.x + q2.y*ka.y + q2.z*ka.z + q2.w*ka.w;
            s[2][1] += q2.x*kb.x + q2.y*kb.y + q2.z*kb.z + q2.w*kb.w;
            s[3][0] += q3.x*ka.x + q3.y*ka.y + q3.z*ka.z + q3.w*ka.w;
            s[3][1] += q3.x*kb.x + q3.y*kb.y + q3.z*kb.z + q3.w*kb.w;
        }
        #pragma unroll
        for (int i = 0; i < 4; i++) {
            const int qrow = qt*AQ + ty*4 + i;
            #pragma unroll
            for (int j = 0; j < 2; j++) {
                const int kcol = kvt*AK + tx*2 + j;
                s[i][j] = (kcol <= qrow) ? s[i][j]*0.125f : -1e9f;
            }
        }
        #pragma unroll
        for (int i = 0; i < 4; i++) {
            float mx = fmaxf(s[i][0], s[i][1]);
            #pragma unroll
            for (int o = 8; o; o >>= 1) mx = fmaxf(mx, __shfl_xor_sync(0xffffffffu, mx, o));
            const float mn = fmaxf(m_i[i], mx);
            const float p0 = expf(s[i][0]-mn), p1 = expf(s[i][1]-mn);
            float rs = p0 + p1;
            #pragma unroll
            for (int o = 8; o; o >>= 1) rs += __shfl_xor_sync(0xffffffffu, rs, o);
            const float alpha = expf(m_i[i]-mn);
            m_i[i] = mn;
            l_i[i] = l_i[i]*alpha + rs;
            #pragma unroll
            for (int j = 0; j < 4; j++) O[i][j] *= alpha;
            Ps[ty*4+i][tx*2+0] = p0;
            Ps[ty*4+i][tx*2+1] = p1;
        }
        __syncthreads();
        #pragma unroll
        for (int k4 = 0; k4 < AK; k4 += 4) {
            float4 v0 = *(const float4*)&Vs[k4+0][tx*4];
            float4 v1 = *(const float4*)&Vs[k4+1][tx*4];
            float4 v2 = *(const float4*)&Vs[k4+2][tx*4];
            float4 v3 = *(const float4*)&Vs[k4+3][tx*4];
            #pragma unroll
            for (int i = 0; i < 4; i++) {
                float4 p = *(const float4*)&Ps[ty*4+i][k4];
                O[i][0] += p.x*v0.x + p.y*v1.x + p.z*v2.x + p.w*v3.x;
                O[i][1] += p.x*v0.y + p.y*v1.y + p.z*v2.y + p.w*v3.y;
                O[i][2] += p.x*v0.z + p.y*v1.z + p.z*v2.z + p.w*v3.z;
                O[i][3] += p.x*v0.w + p.y*v1.w + p.z*v2.w + p.w*v3.w;
            }
        }
    }
    #pragma unroll
    for (int i = 0; i < 4; i++) {
        const float invl = 1.0f/l_i[i];
        const size_t off = (size_t)(b*T_ + qt*AQ + ty*4 + i)*H_ + nh*HD_ + tx*4;
        #pragma unroll
        for (int j = 0; j < 4; j++) {
            float v = O[i][j]*invl;
            __nv_bfloat16 h, l; bsplit(v, h, l);
            att_hi[off + j] = h;
            att_lo[off + j] = l;
        }
    }
}

// ---------------- SwiGLU: act = silu(g) * u -> bf16 hi/lo ----------------
__global__ void silu_kernel(const float* __restrict__ g, const float* __restrict__ u,
                            __nv_bfloat16* __restrict__ ahi, __nv_bfloat16* __restrict__ alo,
                            int n) {
    const int i = blockIdx.x*256 + threadIdx.x;
    if (i < n) {
        const float gv = g[i];
        float v = (gv / (1.0f + expf(-gv))) * u[i];
        __nv_bfloat16 h, l; bsplit(v, h, l);
        ahi[i] = h; alo[i] = l;
    }
}

// ---------------- head: logits = latent@W + b, clamp, softmax ----------------
__global__ void head_kernel(const float* __restrict__ latent, const float* __restrict__ W,
                            const float* __restrict__ bias, const float* __restrict__ temp,
                            float* __restrict__ out) {
    const int m = blockIdx.x;
    __shared__ float xs[H_];
    __shared__ float red[8][32];
    const float* row = latent + (size_t)m*H_;
    for (int i = threadIdx.x; i < H_; i += 256) xs[i] = row[i];
    __syncthreads();
    const int n  = threadIdx.x & 31;
    const int ch = threadIdx.x >> 5;
    float p = 0.f;
    if (n < 31) {
        const int k0 = ch*128;
        for (int k = k0; k < k0 + 128; k++) p += xs[k]*W[(size_t)k*31 + n];
    }
    red[ch][n] = p;
    __syncthreads();
    if (threadIdx.x < 32) {
        float v = 0.f;
        if (n < 31) {
            #pragma unroll
            for (int c = 0; c < 8; c++) v += red[c][n];
            v += bias[n];
            v = fminf(fmaxf(v, -10.0f), 10.0f);
            out[(size_t)M_*31 + (size_t)m*31 + n] = v;
        }
        const float t = *temp;
        float mx = (n < 31) ? v : -1e30f;
        #pragma unroll
        for (int o = 16; o; o >>= 1) mx = fmaxf(mx, __shfl_xor_sync(0xffffffffu, mx, o));
        const float ev = (n < 31) ? expf((v - mx)/t) : 0.f;
        float sm = ev;
        #pragma unroll
        for (int o = 16; o; o >>= 1) sm += __shfl_xor_sync(0xffffffffu, sm, o);
        if (n < 31) out[(size_t)m*31 + n] = ev/sm;
    }
}

// ---------------- launcher ----------------
extern "C" void kernel_launch(void* const* d_in, const int* in_sizes, int n_in,
                              void* d_out, int out_size) {
    (void)in_sizes; (void)n_in; (void)out_size;
    const float* x       = (const float*)d_in[0];
    const float* temp    = (const float*)d_in[1];
    const float* state_W = (const float*)d_in[2];
    const float* state_b = (const float*)d_in[3];
    const float* ln1     = (const float*)d_in[4];
    const float* ln2     = (const float*)d_in[5];
    const float* Wqkv    = (const float*)d_in[6];
    const float* Aqkv    = (const float*)d_in[7];
    const float* Bqkv    = (const float*)d_in[8];
    const float* Wo      = (const float*)d_in[9];
    const float* Ao      = (const float*)d_in[10];
    const float* Bo      = (const float*)d_in[11];
    const float* Wgu     = (const float*)d_in[12];
    const float* Agu     = (const float*)d_in[13];
    const float* Bgu     = (const float*)d_in[14];
    const float* Wd      = (const float*)d_in[15];
    const float* Ad      = (const float*)d_in[16];
    const float* Bd      = (const float*)d_in[17];
    const float* ln_f    = (const float*)d_in[18];
    const float* head_W  = (const float*)d_in[19];
    const float* head_b  = (const float*)d_in[20];
    float* out = (float*)d_out;

    float *p_h, *p_hn, *p_qkv, *p_gu;
    __nv_bfloat16 *p_hn_hi, *p_hn_lo, *p_att_hi, *p_att_lo, *p_act_hi, *p_act_lo;
    __nv_bfloat16 *pWq_hi, *pWq_lo, *pWo_hi, *pWo_lo, *pWgu_hi, *pWgu_lo, *pWd_hi, *pWd_lo;
    cudaGetSymbolAddress((void**)&p_h,     g_h);
    cudaGetSymbolAddress((void**)&p_hn,    g_hn);
    cudaGetSymbolAddress((void**)&p_qkv,   g_qkv);
    cudaGetSymbolAddress((void**)&p_gu,    g_gu);
    cudaGetSymbolAddress((void**)&p_hn_hi, g_hn_hi);
    cudaGetSymbolAddress((void**)&p_hn_lo, g_hn_lo);
    cudaGetSymbolAddress((void**)&p_att_hi,g_att_hi);
    cudaGetSymbolAddress((void**)&p_att_lo,g_att_lo);
    cudaGetSymbolAddress((void**)&p_act_hi,g_act_hi);
    cudaGetSymbolAddress((void**)&p_act_lo,g_act_lo);
    cudaGetSymbolAddress((void**)&pWq_hi,  g_Wq_hi);
    cudaGetSymbolAddress((void**)&pWq_lo,  g_Wq_lo);
    cudaGetSymbolAddress((void**)&pWo_hi,  g_Wo_hi);
    cudaGetSymbolAddress((void**)&pWo_lo,  g_Wo_lo);
    cudaGetSymbolAddress((void**)&pWgu_hi, g_Wgu_hi);
    cudaGetSymbolAddress((void**)&pWgu_lo, g_Wgu_lo);
    cudaGetSymbolAddress((void**)&pWd_hi,  g_Wd_hi);
    cudaGetSymbolAddress((void**)&pWd_lo,  g_Wd_lo);

    cudaFuncSetAttribute(gemm_bf16x3, cudaFuncAttributeMaxDynamicSharedMemorySize, GSMEM_BYTES);

    // ---- fold LoRA + transpose + bf16-split effective weights ----
    fold_kernel<<<dim3(32, 32, 24), 256>>>(Wqkv, Aqkv, Bqkv, pWq_hi,  pWq_lo,  H_, H_);
    fold_kernel<<<dim3(32, 32,  8), 256>>>(Wo,   Ao,   Bo,   pWo_hi,  pWo_lo,  H_, H_);
    fold_kernel<<<dim3(32, 88, 16), 256>>>(Wgu,  Agu,  Bgu,  pWgu_hi, pWgu_lo, H_, F_);
    fold_kernel<<<dim3(88, 32,  8), 256>>>(Wd,   Ad,   Bd,   pWd_hi,  pWd_lo,  F_, H_);

    // ---- embed + first rms ----
    init_h_kernel<<<dim3(4, M_), 256>>>(x, state_W, state_b);
    rms_kernel<<<M_, 256>>>(p_h, ln1, p_hn, p_hn_hi, p_hn_lo);

    // ---- layers ----
    for (int l = 0; l < L_; l++) {
        // QKV: 3 matrices via z
        gemm_bf16x3<<<dim3(8, 16, 3), 128, GSMEM_BYTES>>>(
            p_hn_hi, p_hn_lo, pWq_hi + (size_t)l*3*HH_, pWq_lo + (size_t)l*3*HH_,
            p_qkv, H_, H_, H_, HH_, MH_, 0);
        rope_kernel<<<dim3(4096, 2), 256>>>(p_qkv);
        attn_kernel<<<dim3(16, 16, 2), 256>>>(p_qkv, p_att_hi, p_att_lo);
        // Wo: split-K=2 -> partials in g_qkv (free after attn)
        gemm_bf16x3<<<dim3(8, 16, 2), 128, GSMEM_BYTES>>>(
            p_att_hi, p_att_lo, pWo_hi + (size_t)l*HH_, pWo_lo + (size_t)l*HH_,
            p_qkv, H_, 512, H_, 0, MH_, 512);
        rms3_kernel<<<M_, 256>>>(p_h, p_qkv, p_qkv + MH_, ln2 + (size_t)l*H_,
                                 p_hn, p_hn_hi, p_hn_lo);
        // GU: 2 matrices via z
        gemm_bf16x3<<<dim3(22, 16, 2), 128, GSMEM_BYTES>>>(
            p_hn_hi, p_hn_lo, pWgu_hi + (size_t)l*2*HF_, pWgu_lo + (size_t)l*2*HF_,
            p_gu, F_, H_, H_, HF_, MF_, 0);
        silu_kernel<<<(int)((MF_ + 255)/256), 256>>>(p_gu, p_gu + MF_, p_act_hi, p_act_lo, (int)MF_);
        // Wd: split-K=2 -> partials in g_gu (free after silu)
        gemm_bf16x3<<<dim3(8, 16, 2), 128, GSMEM_BYTES>>>(
            p_act_hi, p_act_lo, pWd_hi + (size_t)l*HF_, pWd_lo + (size_t)l*HF_,
            p_gu, H_, 1408, F_, 0, MH_, 1408);
        // fused residual + next norm (ln1 of next layer, or ln_f at the end)
        const float* wnext = (l < L_-1) ? (ln1 + (size_t)(l+1)*H_) : ln_f;
        rms3_kernel<<<M_, 256>>>(p_h, p_gu, p_gu + MH_, wnext,
                                 p_hn, p_hn_hi, p_hn_lo);
    }

    // ---- head + softmax ----
    head_kernel<<<M_, 256>>>(p_hn, head_W, head_b, temp, out);
}

// round 15
// speedup vs baseline: 3.2593x; 1.3062x over previous
#include <cuda_runtime.h>
#include <cuda_bf16.h>
#include <math.h>
#include <stdint.h>

// ---------------- problem constants ----------------
#define B_   2
#define T_   1024
#define NT_  30
#define H_   1024
#define L_   8
#define F_   2816
#define NH_  16
#define HD_  64
#define R_   16
#define M_   (B_*T_)                 // 2048 tokens
#define MH_  ((size_t)M_*H_)
#define HH_  ((size_t)H_*H_)
#define HF_  ((size_t)H_*F_)
#define MF_  ((size_t)M_*F_)

// ---------------- scratch (device globals: no allocation allowed) ----------------
__device__ float g_h  [M_*H_];       // fp32 residual stream
__device__ float g_hn [M_*H_];       // fp32 rms out (head input)
__device__ float g_qkv[3*M_*H_];     // qkv; later Wo split-K partials (2*MH)
__device__ float g_gu [2*M_*F_];     // gu;  later Wd split-K partials (2*MH)
// bf16 hi/lo activation operands
__device__ __nv_bfloat16 g_hn_hi [M_*H_], g_hn_lo [M_*H_];
__device__ __nv_bfloat16 g_att_hi[M_*H_], g_att_lo[M_*H_];
__device__ __nv_bfloat16 g_act_hi[M_*F_], g_act_lo[M_*F_];
// per-head attention operands: Q,K [bh][t][hd]; VT [bh][hd][t]
#define BH_  (B_*NH_)
#define QKN_ ((size_t)BH_*T_*HD_)
__device__ __nv_bfloat16 g_qr_hi[QKN_], g_qr_lo[QKN_];
__device__ __nv_bfloat16 g_kr_hi[QKN_], g_kr_lo[QKN_];
__device__ __nv_bfloat16 g_vt_hi[QKN_], g_vt_lo[QKN_];
// fused+TRANSPOSED effective weights as bf16 hi/lo: W_T[n][k]
__device__ __nv_bfloat16 g_Wq_hi [L_*3*H_*H_], g_Wq_lo [L_*3*H_*H_];
__device__ __nv_bfloat16 g_Wo_hi [L_*H_*H_],   g_Wo_lo [L_*H_*H_];
__device__ __nv_bfloat16 g_Wgu_hi[L_*2*H_*F_], g_Wgu_lo[L_*2*H_*F_];
__device__ __nv_bfloat16 g_Wd_hi [L_*F_*H_],   g_Wd_lo [L_*F_*H_];

// ---------------- helpers ----------------
__device__ __forceinline__ uint32_t s2u(const void* p) {
    uint32_t a;
    asm("{ .reg .u64 t; cvta.to.shared.u64 t, %1; cvt.u32.u64 %0, t; }" : "=r"(a) : "l"(p));
    return a;
}
__device__ __forceinline__ void bsplit(float v, __nv_bfloat16& h, __nv_bfloat16& l) {
    h = __float2bfloat16(v);
    l = __float2bfloat16(v - __bfloat162float(h));
}
__device__ __forceinline__ void cpa16(uint32_t s, const void* g) {
    asm volatile("cp.async.ca.shared.global [%0], [%1], 16;" :: "r"(s), "l"(g) : "memory");
}
__device__ __forceinline__ void cp_commit() {
    asm volatile("cp.async.commit_group;" ::: "memory");
}
template<int NN> __device__ __forceinline__ void cp_wait() {
    asm volatile("cp.async.wait_group %0;" :: "n"(NN) : "memory");
}
__device__ __forceinline__ void mma16816(float* c, const uint32_t* a, const uint32_t* b) {
    asm volatile("mma.sync.aligned.m16n8k16.row.col.f32.bf16.bf16.f32 "
        "{%0,%1,%2,%3}, {%4,%5,%6,%7}, {%8,%9}, {%0,%1,%2,%3};"
        : "+f"(c[0]), "+f"(c[1]), "+f"(c[2]), "+f"(c[3])
        : "r"(a[0]), "r"(a[1]), "r"(a[2]), "r"(a[3]), "r"(b[0]), "r"(b[1]));
}
__device__ __forceinline__ void ldm_x4(uint32_t* r, uint32_t addr) {
    asm volatile("ldmatrix.sync.aligned.m8n8.x4.shared.b16 {%0,%1,%2,%3}, [%4];"
        : "=r"(r[0]), "=r"(r[1]), "=r"(r[2]), "=r"(r[3]) : "r"(addr));
}
__device__ __forceinline__ uint32_t bf2u(__nv_bfloat16 a, __nv_bfloat16 b) {
    uint16_t ua = *reinterpret_cast<uint16_t*>(&a);
    uint16_t ub = *reinterpret_cast<uint16_t*>(&b);
    return (uint32_t)ua | ((uint32_t)ub << 16);
}
__device__ __forceinline__ uint32_t pack_hi(float x, float y, float& rx, float& ry) {
    __nv_bfloat16 hx = __float2bfloat16(x), hy = __float2bfloat16(y);
    rx = x - __bfloat162float(hx);
    ry = y - __bfloat162float(hy);
    return bf2u(hx, hy);
}
__device__ __forceinline__ uint32_t pack_lo(float x, float y) {
    return bf2u(__float2bfloat16(x), __float2bfloat16(y));
}

// ============ bf16x3 tensor-core GEMM: C[M,N] = A @ B^T (slice of K) ============
#define OPT_B   8192u
#define STAGE_B 32768u
#define NSTG    3
#define GSMEM_BYTES (NSTG*STAGE_B)   // 98304

__global__ void __launch_bounds__(128)
gemm_bf16x3(const __nv_bfloat16* __restrict__ Ahi, const __nv_bfloat16* __restrict__ Alo,
            const __nv_bfloat16* __restrict__ Bhi, const __nv_bfloat16* __restrict__ Blo,
            float* __restrict__ C, int N, int Klen, int lda,
            size_t strideB, size_t strideC, int kOffPerZ)
{
    extern __shared__ uint32_t smu[];
    const int kOff = (int)blockIdx.z * kOffPerZ;
    Bhi += (size_t)blockIdx.z * strideB;
    Blo += (size_t)blockIdx.z * strideB;
    C   += (size_t)blockIdx.z * strideC;

    const int tid  = threadIdx.x;
    const int lane = tid & 31;
    const int wid  = tid >> 5;
    const int g    = lane >> 2;
    const int tg   = lane & 3;
    const int rbase = (wid & 1) * 64;
    const int cbase = (wid >> 1) * 64;
    const int row0 = blockIdx.y * 128;
    const int col0 = blockIdx.x * 128;

    const uint32_t smb = s2u(smu);
    const int ld_m  = tid >> 2;
    const int ld_kc = tid & 3;

    auto load_stage = [&](int st, int ch) {
        const uint32_t base = smb + (uint32_t)st * STAGE_B;
        #pragma unroll
        for (int u = 0; u < 4; u++) {
            const int m = ld_m + u * 32;
            const uint32_t sw = (uint32_t)((m * 4 + (ld_kc ^ ((m >> 1) & 3))) << 4);
            const size_t ga = (size_t)(row0 + m) * lda + kOff + ch * 32 + ld_kc * 8;
            const size_t gb = (size_t)(col0 + m) * lda + kOff + ch * 32 + ld_kc * 8;
            cpa16(base +            sw, Ahi + ga);
            cpa16(base + OPT_B    + sw, Alo + ga);
            cpa16(base + 2*OPT_B  + sw, Bhi + gb);
            cpa16(base + 3*OPT_B  + sw, Blo + gb);
        }
        cp_commit();
    };

    const int li = lane & 7;
    const uint32_t aRowBase = (uint32_t)(rbase + li + ((lane >> 3) & 1) * 8);
    const uint32_t aKcSel   = (uint32_t)(lane >> 4);
    const uint32_t bN0      = (uint32_t)(cbase + li + ((lane >> 4) << 3));
    const uint32_t bKcSel   = (uint32_t)((lane >> 3) & 1);
    const uint32_t bXor     = (bN0 >> 1) & 3u;

    float acc[4][8][4];
    #pragma unroll
    for (int mt = 0; mt < 4; mt++)
        #pragma unroll
        for (int nt = 0; nt < 8; nt++)
            #pragma unroll
            for (int c = 0; c < 4; c++) acc[mt][nt][c] = 0.f;

    const int nch = Klen / 32;
    load_stage(0, 0);
    load_stage(1, 1);

    for (int ch = 0; ch < nch; ch++) {
        const int st = ch % NSTG;
        if (ch < nch - 1) cp_wait<1>();
        else              cp_wait<0>();
        __syncthreads();
        if (ch + 2 < nch) load_stage((ch + 2) % NSTG, ch + 2);

        const uint32_t sbase = smb + (uint32_t)st * STAGE_B;
        #pragma unroll
        for (int ks = 0; ks < 2; ks++) {
            uint32_t bh[8][2], bl[8][2];
            {
                const uint32_t bkc = (uint32_t)(ks * 2) + bKcSel;
                const uint32_t a0 = sbase + 2*OPT_B + ((bN0 * 4u + (bkc ^ bXor)) << 4);
                #pragma unroll
                for (int gg = 0; gg < 4; gg++) {
                    uint32_t r[4];
                    ldm_x4(r, a0 + (uint32_t)(gg * 1024));
                    bh[gg*2+0][0]=r[0]; bh[gg*2+0][1]=r[1];
                    bh[gg*2+1][0]=r[2]; bh[gg*2+1][1]=r[3];
                    ldm_x4(r, a0 + OPT_B + (uint32_t)(gg * 1024));
                    bl[gg*2+0][0]=r[0]; bl[gg*2+0][1]=r[1];
                    bl[gg*2+1][0]=r[2]; bl[gg*2+1][1]=r[3];
                }
            }
            #pragma unroll
            for (int mt = 0; mt < 4; mt++) {
                const uint32_t arow = aRowBase + (uint32_t)(mt * 16);
                const uint32_t akc  = (uint32_t)(ks * 2) + aKcSel;
                const uint32_t aH = sbase + ((arow * 4u + (akc ^ ((arow >> 1) & 3u))) << 4);
                uint32_t ah[4], al[4];
                ldm_x4(ah, aH);
                ldm_x4(al, aH + OPT_B);
                #pragma unroll
                for (int nt = 0; nt < 8; nt++) {
                    mma16816(acc[mt][nt], ah, bh[nt]);
                    mma16816(acc[mt][nt], ah, bl[nt]);
                    mma16816(acc[mt][nt], al, bh[nt]);
                }
            }
        }
        __syncthreads();
    }

    #pragma unroll
    for (int mt = 0; mt < 4; mt++) {
        #pragma unroll
        for (int nt = 0; nt < 8; nt++) {
            const int row = row0 + rbase + mt * 16 + g;
            const int col = col0 + cbase + nt * 8 + 2 * tg;
            *(float2*)(C + (size_t)row * N + col)       = make_float2(acc[mt][nt][0], acc[mt][nt][1]);
            *(float2*)(C + (size_t)(row + 8) * N + col) = make_float2(acc[mt][nt][2], acc[mt][nt][3]);
        }
    }
}

// ---------------- LoRA fold: WeffT[n][k] (bf16 hi/lo) ----------------
__global__ void fold_kernel(const float* __restrict__ W, const float* __restrict__ A,
                            const float* __restrict__ Bm,
                            __nv_bfloat16* __restrict__ Whi, __nv_bfloat16* __restrict__ Wlo,
                            int KK, int N) {
    const int mat = blockIdx.z;
    const int i0 = blockIdx.x * 32, j0 = blockIdx.y * 32;
    W   += (size_t)mat * KK * N;
    A   += (size_t)mat * R_ * KK;
    Bm  += (size_t)mat * N * R_;
    Whi += (size_t)mat * (size_t)KK * N;
    Wlo += (size_t)mat * (size_t)KK * N;

    __shared__ float Wt[32][33];
    __shared__ float As[R_][33];
    __shared__ float Bs[32][R_+1];
    const int tx = threadIdx.x & 31, ty = threadIdx.x >> 5;
    #pragma unroll
    for (int u = 0; u < 4; u++) {
        int ii = ty * 4 + u;
        Wt[ii][tx] = W[(size_t)(i0 + ii) * N + j0 + tx];
    }
    #pragma unroll
    for (int u = 0; u < 2; u++) {
        int id = threadIdx.x + u * 256;
        As[id >> 5][id & 31] = A[(size_t)(id >> 5) * KK + i0 + (id & 31)];
    }
    #pragma unroll
    for (int u = 0; u < 2; u++) {
        int id = threadIdx.x + u * 256;
        Bs[id >> 4][id & 15] = Bm[(size_t)(j0 + (id >> 4)) * R_ + (id & 15)];
    }
    __syncthreads();
    #pragma unroll
    for (int u = 0; u < 4; u++) {
        int jj = ty * 4 + u;
        float s = 0.f;
        #pragma unroll
        for (int r = 0; r < R_; r++) s += As[r][tx] * Bs[jj][r];
        float v = Wt[tx][jj] + 2.0f * s;
        __nv_bfloat16 h, l; bsplit(v, h, l);
        size_t off = (size_t)(j0 + jj) * KK + i0 + tx;
        Whi[off] = h; Wlo[off] = l;
    }
}

// ---------------- h = x @ state_W + state_b ----------------
__global__ void init_h_kernel(const float* __restrict__ x, const float* __restrict__ W,
                              const float* __restrict__ b) {
    const int m = blockIdx.y;
    const int j = blockIdx.x*256 + threadIdx.x;
    __shared__ float xs[NT_];
    if (threadIdx.x < NT_) xs[threadIdx.x] = x[(size_t)m*NT_ + threadIdx.x];
    __syncthreads();
    float s = b[j];
    #pragma unroll
    for (int k = 0; k < NT_; k++) s += xs[k]*W[(size_t)k*H_ + j];
    g_h[(size_t)m*H_ + j] = s;
}

// ---------------- RMSNorm (plain) ----------------
__global__ void rms_kernel(const float* __restrict__ in, const float* __restrict__ w,
                           float* __restrict__ out,
                           __nv_bfloat16* __restrict__ ohi, __nv_bfloat16* __restrict__ olo) {
    const int m = blockIdx.x;
    const float* row = in + (size_t)m*H_;
    float s = 0.f;
    for (int i = threadIdx.x; i < H_; i += 256) { float v = row[i]; s += v*v; }
    __shared__ float red[8];
    #pragma unroll
    for (int o = 16; o; o >>= 1) s += __shfl_xor_sync(0xffffffffu, s, o);
    if ((threadIdx.x & 31) == 0) red[threadIdx.x >> 5] = s;
    __syncthreads();
    if (threadIdx.x < 8) {
        float v = red[threadIdx.x];
        #pragma unroll
        for (int o = 4; o; o >>= 1) v += __shfl_xor_sync(0xffu, v, o);
        if (threadIdx.x == 0) red[0] = v;
    }
    __syncthreads();
    const float inv = rsqrtf(red[0]*(1.0f/H_) + 1e-6f);
    for (int i = threadIdx.x; i < H_; i += 256) {
        float v = row[i]*inv*w[i];
        out[(size_t)m*H_ + i] = v;
        __nv_bfloat16 h, l; bsplit(v, h, l);
        ohi[(size_t)m*H_ + i] = h;
        olo[(size_t)m*H_ + i] = l;
    }
}

// ---------------- fused: h += P0 + P1; rms(h) ----------------
__global__ void rms3_kernel(float* __restrict__ hbuf,
                            const float* __restrict__ P0, const float* __restrict__ P1,
                            const float* __restrict__ w,
                            float* __restrict__ out,
                            __nv_bfloat16* __restrict__ ohi, __nv_bfloat16* __restrict__ olo) {
    const int m = blockIdx.x;
    const size_t base = (size_t)m * H_;
    float v4[4];
    float s = 0.f;
    #pragma unroll
    for (int u = 0; u < 4; u++) {
        const int i = threadIdx.x + u * 256;
        float v = hbuf[base + i] + P0[base + i] + P1[base + i];
        v4[u] = v;
        s += v * v;
        hbuf[base + i] = v;
    }
    __shared__ float red[8];
    #pragma unroll
    for (int o = 16; o; o >>= 1) s += __shfl_xor_sync(0xffffffffu, s, o);
    if ((threadIdx.x & 31) == 0) red[threadIdx.x >> 5] = s;
    __syncthreads();
    if (threadIdx.x < 8) {
        float v = red[threadIdx.x];
        #pragma unroll
        for (int o = 4; o; o >>= 1) v += __shfl_xor_sync(0xffu, v, o);
        if (threadIdx.x == 0) red[0] = v;
    }
    __syncthreads();
    const float inv = rsqrtf(red[0]*(1.0f/H_) + 1e-6f);
    #pragma unroll
    for (int u = 0; u < 4; u++) {
        const int i = threadIdx.x + u * 256;
        float v = v4[u] * inv * w[i];
        out[base + i] = v;
        __nv_bfloat16 h, l; bsplit(v, h, l);
        ohi[base + i] = h;
        olo[base + i] = l;
    }
}

// ---------------- qkv prep: rope(Q,K) + bf16 hi/lo, V transposed ----------------
// Q,K out: [bh][t][hd]; VT out: [bh][hd][t]
__global__ void qkv_prep(const float* __restrict__ qkv,
                         __nv_bfloat16* __restrict__ Qh, __nv_bfloat16* __restrict__ Ql,
                         __nv_bfloat16* __restrict__ Kh, __nv_bfloat16* __restrict__ Kl,
                         __nv_bfloat16* __restrict__ Vh, __nv_bfloat16* __restrict__ Vl) {
    const int t0 = blockIdx.x * 64, nh = blockIdx.y, b = blockIdx.z;
    const int bh = b * NH_ + nh;
    const int tid = threadIdx.x;
    __shared__ __nv_bfloat16 vh_s[64][65], vl_s[64][65];
    #pragma unroll
    for (int u = 0; u < 8; u++) {
        const int idx = tid + u * 256;            // 64 rows x 32 freqs
        const int r = idx >> 5, i = idx & 31;
        const int t = t0 + r;
        const size_t gin  = (size_t)(b*T_ + t) * H_ + nh * HD_;
        const size_t gout = ((size_t)bh * T_ + t) * HD_;
        const float inv = expf(-(float)i * (1.0f/32.0f) * 9.210340371976184f);
        const float ang = (float)t * inv;
        const float c = cosf(ang), sn = sinf(ang);
        const float q1 = qkv[gin + i],       q2 = qkv[gin + i + 32];
        const float k1 = qkv[MH_ + gin + i], k2 = qkv[MH_ + gin + i + 32];
        __nv_bfloat16 h, l;
        bsplit(q1*c - q2*sn, h, l); Qh[gout + i]      = h; Ql[gout + i]      = l;
        bsplit(q2*c + q1*sn, h, l); Qh[gout + i + 32] = h; Ql[gout + i + 32] = l;
        bsplit(k1*c - k2*sn, h, l); Kh[gout + i]      = h; Kl[gout + i]      = l;
        bsplit(k2*c + k1*sn, h, l); Kh[gout + i + 32] = h; Kl[gout + i + 32] = l;
    }
    #pragma unroll
    for (int u = 0; u < 16; u++) {
        const int idx = tid + u * 256;            // 64 t x 64 hd
        const int r = idx >> 6, cd = idx & 63;
        const float v = qkv[2*MH_ + (size_t)(b*T_ + t0 + r) * H_ + nh * HD_ + cd];
        __nv_bfloat16 h, l; bsplit(v, h, l);
        vh_s[cd][r] = h; vl_s[cd][r] = l;
    }
    __syncthreads();
    #pragma unroll
    for (int u = 0; u < 16; u++) {
        const int idx = tid + u * 256;
        const int hd = idx >> 6, tt = idx & 63;
        const size_t go = ((size_t)bh * HD_ + hd) * T_ + t0 + tt;
        Vh[go] = vh_s[hd][tt];
        Vl[go] = vl_s[hd][tt];
    }
}

// ---------------- tensor-core flash attention (bf16x3, causal) ----------------
// CTA = (qt, bh): 64 q rows, 4 warps x 16 rows. kv tiles of 64, double buffered.
#define ATT_SMEM 81920   // Q hi/lo 16KB + 2 KV stages x 32KB

__global__ void __launch_bounds__(128)
attn_mma(const __nv_bfloat16* __restrict__ Qh, const __nv_bfloat16* __restrict__ Ql,
         const __nv_bfloat16* __restrict__ Kh, const __nv_bfloat16* __restrict__ Kl,
         const __nv_bfloat16* __restrict__ Vh, const __nv_bfloat16* __restrict__ Vl,
         __nv_bfloat16* __restrict__ att_hi, __nv_bfloat16* __restrict__ att_lo)
{
    extern __shared__ uint32_t smu[];
    const int qt = (int)gridDim.x - 1 - (int)blockIdx.x;   // long CTAs first
    const int bh = blockIdx.y;
    const int b = bh >> 4, nh = bh & 15;
    const int tid = threadIdx.x, lane = tid & 31, wid = tid >> 5;
    const int g = lane >> 2, tg = lane & 3, li = lane & 7;
    const int wrow = wid * 16;
    const uint32_t smb = s2u(smu);
    const uint32_t QLOF = 8192u, KVOF = 16384u;

    // load Q tile once (group)
    {
        const size_t gq = ((size_t)bh * T_ + qt * 64) * HD_;
        #pragma unroll
        for (int u = 0; u < 4; u++) {
            const int idx = tid + u * 128;
            const int r = idx >> 3, kc = idx & 7;
            const uint32_t sw = (uint32_t)(r * 128 + ((kc ^ (r & 7)) << 4));
            cpa16(smb + sw,        Qh + gq + (size_t)r * HD_ + kc * 8);
            cpa16(smb + QLOF + sw, Ql + gq + (size_t)r * HD_ + kc * 8);
        }
        cp_commit();
    }
    auto load_kv = [&](int st, int kvt) {
        const uint32_t base = smb + KVOF + (uint32_t)st * 32768u;
        const size_t gk = ((size_t)bh * T_ + kvt * 64) * HD_;
        const size_t gv = (size_t)bh * HD_ * T_ + kvt * 64;
        #pragma unroll
        for (int u = 0; u < 4; u++) {
            const int idx = tid + u * 128;
            const int r = idx >> 3, kc = idx & 7;
            const uint32_t sw = (uint32_t)(r * 128 + ((kc ^ (r & 7)) << 4));
            cpa16(base +          sw, Kh + gk + (size_t)r * HD_ + kc * 8);
            cpa16(base + 8192u  + sw, Kl + gk + (size_t)r * HD_ + kc * 8);
            cpa16(base + 16384u + sw, Vh + gv + (size_t)r * T_ + kc * 8);
            cpa16(base + 24576u + sw, Vl + gv + (size_t)r * T_ + kc * 8);
        }
        cp_commit();
    };

    float m0 = -1e30f, m1 = -1e30f, l0 = 0.f, l1 = 0.f;
    float Oacc[8][4];
    #pragma unroll
    for (int nt = 0; nt < 8; nt++)
        #pragma unroll
        for (int c = 0; c < 4; c++) Oacc[nt][c] = 0.f;

    const int nkv = qt + 1;
    load_kv(0, 0);

    const uint32_t aRow  = (uint32_t)(wrow + li + ((lane >> 3) & 1) * 8);
    const uint32_t aKcS  = (uint32_t)(lane >> 4);
    const uint32_t bRow0 = (uint32_t)(li + ((lane >> 4) << 3));
    const uint32_t bKcS  = (uint32_t)((lane >> 3) & 1);

    for (int kvt = 0; kvt < nkv; kvt++) {
        const int st = kvt & 1;
        if (kvt + 1 < nkv) load_kv(st ^ 1, kvt + 1);
        if (kvt + 1 < nkv) cp_wait<1>(); else cp_wait<0>();
        __syncthreads();
        const uint32_t kbase = smb + KVOF + (uint32_t)st * 32768u;

        // ---- S = Q @ K^T (bf16x3) ----
        float sacc[8][4];
        #pragma unroll
        for (int nt = 0; nt < 8; nt++)
            #pragma unroll
            for (int c = 0; c < 4; c++) sacc[nt][c] = 0.f;

        #pragma unroll
        for (int ks = 0; ks < 4; ks++) {
            const uint32_t kcA = (uint32_t)(2 * ks) + aKcS;
            const uint32_t qaddr = smb + aRow * 128 + ((kcA ^ (aRow & 7)) << 4);
            uint32_t aH[4], aL[4];
            ldm_x4(aH, qaddr);
            ldm_x4(aL, qaddr + QLOF);
            const uint32_t kcB = (uint32_t)(2 * ks) + bKcS;
            uint32_t bH[8][2], bL[8][2];
            #pragma unroll
            for (int gg = 0; gg < 4; gg++) {
                const uint32_t rb = bRow0 + (uint32_t)(gg * 16);
                const uint32_t ad = kbase + rb * 128 + ((kcB ^ (rb & 7)) << 4);
                uint32_t r4[4];
                ldm_x4(r4, ad);
                bH[gg*2][0]=r4[0]; bH[gg*2][1]=r4[1]; bH[gg*2+1][0]=r4[2]; bH[gg*2+1][1]=r4[3];
                ldm_x4(r4, ad + 8192u);
                bL[gg*2][0]=r4[0]; bL[gg*2][1]=r4[1]; bL[gg*2+1][0]=r4[2]; bL[gg*2+1][1]=r4[3];
            }
            #pragma unroll
            for (int nt = 0; nt < 8; nt++) {
                mma16816(sacc[nt], aH, bH[nt]);
                mma16816(sacc[nt], aH, bL[nt]);
                mma16816(sacc[nt], aL, bH[nt]);
            }
        }

        // ---- scale + causal mask (only diagonal tile) ----
        if (kvt == qt) {
            const int r0 = wrow + g, r1 = r0 + 8;
            #pragma unroll
            for (int nt = 0; nt < 8; nt++) {
                const int c0 = nt * 8 + 2 * tg, c1 = c0 + 1;
                sacc[nt][0] = (c0 <= r0) ? sacc[nt][0] * 0.125f : -1e9f;
                sacc[nt][1] = (c1 <= r0) ? sacc[nt][1] * 0.125f : -1e9f;
                sacc[nt][2] = (c0 <= r1) ? sacc[nt][2] * 0.125f : -1e9f;
                sacc[nt][3] = (c1 <= r1) ? sacc[nt][3] * 0.125f : -1e9f;
            }
        } else {
            #pragma unroll
            for (int nt = 0; nt < 8; nt++)
                #pragma unroll
                for (int c = 0; c < 4; c++) sacc[nt][c] *= 0.125f;
        }

        // ---- online softmax (rows g and g+8; quad reduce over tg lanes) ----
        float mx0 = sacc[0][0], mx1 = sacc[0][2];
        #pragma unroll
        for (int nt = 0; nt < 8; nt++) {
            mx0 = fmaxf(mx0, fmaxf(sacc[nt][0], sacc[nt][1]));
            mx1 = fmaxf(mx1, fmaxf(sacc[nt][2], sacc[nt][3]));
        }
        mx0 = fmaxf(mx0, __shfl_xor_sync(0xffffffffu, mx0, 1));
        mx0 = fmaxf(mx0, __shfl_xor_sync(0xffffffffu, mx0, 2));
        mx1 = fmaxf(mx1, __shfl_xor_sync(0xffffffffu, mx1, 1));
        mx1 = fmaxf(mx1, __shfl_xor_sync(0xffffffffu, mx1, 2));
        const float mn0 = fmaxf(m0, mx0), mn1 = fmaxf(m1, mx1);
        const float al0 = __expf(m0 - mn0), al1 = __expf(m1 - mn1);
        float rs0 = 0.f, rs1 = 0.f;
        #pragma unroll
        for (int nt = 0; nt < 8; nt++) {
            sacc[nt][0] = __expf(sacc[nt][0] - mn0); rs0 += sacc[nt][0];
            sacc[nt][1] = __expf(sacc[nt][1] - mn0); rs0 += sacc[nt][1];
            sacc[nt][2] = __expf(sacc[nt][2] - mn1); rs1 += sacc[nt][2];
            sacc[nt][3] = __expf(sacc[nt][3] - mn1); rs1 += sacc[nt][3];
        }
        rs0 += __shfl_xor_sync(0xffffffffu, rs0, 1);
        rs0 += __shfl_xor_sync(0xffffffffu, rs0, 2);
        rs1 += __shfl_xor_sync(0xffffffffu, rs1, 1);
        rs1 += __shfl_xor_sync(0xffffffffu, rs1, 2);
        l0 = l0 * al0 + rs0; l1 = l1 * al1 + rs1;
        m0 = mn0; m1 = mn1;
        #pragma unroll
        for (int nt = 0; nt < 8; nt++) {
            Oacc[nt][0] *= al0; Oacc[nt][1] *= al0;
            Oacc[nt][2] *= al1; Oacc[nt][3] *= al1;
        }

        // ---- O += P @ V^T (P fragments come straight from S accumulators) ----
        const uint32_t vbase = kbase + 16384u;
        #pragma unroll
        for (int ks = 0; ks < 4; ks++) {
            const int j0 = 2 * ks, j1 = j0 + 1;
            float r00, r01, r02, r03, r10, r11, r12, r13;
            uint32_t aPh[4], aPl[4];
            aPh[0] = pack_hi(sacc[j0][0], sacc[j0][1], r00, r01);
            aPh[1] = pack_hi(sacc[j0][2], sacc[j0][3], r02, r03);
            aPh[2] = pack_hi(sacc[j1][0], sacc[j1][1], r10, r11);
            aPh[3] = pack_hi(sacc[j1][2], sacc[j1][3], r12, r13);
            aPl[0] = pack_lo(r00, r01); aPl[1] = pack_lo(r02, r03);
            aPl[2] = pack_lo(r10, r11); aPl[3] = pack_lo(r12, r13);
            const uint32_t kcV = (uint32_t)(2 * ks) + bKcS;
            uint32_t vH[8][2], vL[8][2];
            #pragma unroll
            for (int gg = 0; gg < 4; gg++) {
                const uint32_t rb = bRow0 + (uint32_t)(gg * 16);
                const uint32_t ad = vbase + rb * 128 + ((kcV ^ (rb & 7)) << 4);
                uint32_t r4[4];
                ldm_x4(r4, ad);
                vH[gg*2][0]=r4[0]; vH[gg*2][1]=r4[1]; vH[gg*2+1][0]=r4[2]; vH[gg*2+1][1]=r4[3];
                ldm_x4(r4, ad + 8192u);
                vL[gg*2][0]=r4[0]; vL[gg*2][1]=r4[1]; vL[gg*2+1][0]=r4[2]; vL[gg*2+1][1]=r4[3];
            }
            #pragma unroll
            for (int nt = 0; nt < 8; nt++) {
                mma16816(Oacc[nt], aPh, vH[nt]);
                mma16816(Oacc[nt], aPh, vL[nt]);
                mma16816(Oacc[nt], aPl, vH[nt]);
            }
        }
        __syncthreads();
    }

    // ---- epilogue: O/l -> att hi/lo [M][H] ----
    const float i0 = 1.f / l0, i1 = 1.f / l1;
    const int trow = qt * 64 + wrow + g;
    const size_t mrow0 = (size_t)(b * T_ + trow) * H_ + nh * HD_;
    const size_t mrow1 = mrow0 + (size_t)8 * H_;
    #pragma unroll
    for (int nt = 0; nt < 8; nt++) {
        const int col = nt * 8 + 2 * tg;
        __nv_bfloat16 h, l;
        float v;
        v = Oacc[nt][0] * i0; bsplit(v, h, l); att_hi[mrow0+col]   = h; att_lo[mrow0+col]   = l;
        v = Oacc[nt][1] * i0; bsplit(v, h, l); att_hi[mrow0+col+1] = h; att_lo[mrow0+col+1] = l;
        v = Oacc[nt][2] * i1; bsplit(v, h, l); att_hi[mrow1+col]   = h; att_lo[mrow1+col]   = l;
        v = Oacc[nt][3] * i1; bsplit(v, h, l); att_hi[mrow1+col+1] = h; att_lo[mrow1+col+1] = l;
    }
}

// ---------------- SwiGLU: act = silu(g) * u -> bf16 hi/lo ----------------
__global__ void silu_kernel(const float* __restrict__ g, const float* __restrict__ u,
                            __nv_bfloat16* __restrict__ ahi, __nv_bfloat16* __restrict__ alo,
                            int n) {
    const int i = blockIdx.x*256 + threadIdx.x;
    if (i < n) {
        const float gv = g[i];
        float v = (gv / (1.0f + expf(-gv))) * u[i];
        __nv_bfloat16 h, l; bsplit(v, h, l);
        ahi[i] = h; alo[i] = l;
    }
}

// ---------------- head: logits = latent@W + b, clamp, softmax ----------------
__global__ void head_kernel(const float* __restrict__ latent, const float* __restrict__ W,
                            const float* __restrict__ bias, const float* __restrict__ temp,
                            float* __restrict__ out) {
    const int m = blockIdx.x;
    __shared__ float xs[H_];
    __shared__ float red[8][32];
    const float* row = latent + (size_t)m*H_;
    for (int i = threadIdx.x; i < H_; i += 256) xs[i] = row[i];
    __syncthreads();
    const int n  = threadIdx.x & 31;
    const int ch = threadIdx.x >> 5;
    float p = 0.f;
    if (n < 31) {
        const int k0 = ch*128;
        for (int k = k0; k < k0 + 128; k++) p += xs[k]*W[(size_t)k*31 + n];
    }
    red[ch][n] = p;
    __syncthreads();
    if (threadIdx.x < 32) {
        float v = 0.f;
        if (n < 31) {
            #pragma unroll
            for (int c = 0; c < 8; c++) v += red[c][n];
            v += bias[n];
            v = fminf(fmaxf(v, -10.0f), 10.0f);
            out[(size_t)M_*31 + (size_t)m*31 + n] = v;
        }
        const float t = *temp;
        float mx = (n < 31) ? v : -1e30f;
        #pragma unroll
        for (int o = 16; o; o >>= 1) mx = fmaxf(mx, __shfl_xor_sync(0xffffffffu, mx, o));
        const float ev = (n < 31) ? expf((v - mx)/t) : 0.f;
        float sm = ev;
        #pragma unroll
        for (int o = 16; o; o >>= 1) sm += __shfl_xor_sync(0xffffffffu, sm, o);
        if (n < 31) out[(size_t)m*31 + n] = ev/sm;
    }
}

// ---------------- launcher ----------------
extern "C" void kernel_launch(void* const* d_in, const int* in_sizes, int n_in,
                              void* d_out, int out_size) {
    (void)in_sizes; (void)n_in; (void)out_size;
    const float* x       = (const float*)d_in[0];
    const float* temp    = (const float*)d_in[1];
    const float* state_W = (const float*)d_in[2];
    const float* state_b = (const float*)d_in[3];
    const float* ln1     = (const float*)d_in[4];
    const float* ln2     = (const float*)d_in[5];
    const float* Wqkv    = (const float*)d_in[6];
    const float* Aqkv    = (const float*)d_in[7];
    const float* Bqkv    = (const float*)d_in[8];
    const float* Wo      = (const float*)d_in[9];
    const float* Ao      = (const float*)d_in[10];
    const float* Bo      = (const float*)d_in[11];
    const float* Wgu     = (const float*)d_in[12];
    const float* Agu     = (const float*)d_in[13];
    const float* Bgu     = (const float*)d_in[14];
    const float* Wd      = (const float*)d_in[15];
    const float* Ad      = (const float*)d_in[16];
    const float* Bd      = (const float*)d_in[17];
    const float* ln_f    = (const float*)d_in[18];
    const float* head_W  = (const float*)d_in[19];
    const float* head_b  = (const float*)d_in[20];
    float* out = (float*)d_out;

    float *p_h, *p_hn, *p_qkv, *p_gu;
    __nv_bfloat16 *p_hn_hi, *p_hn_lo, *p_att_hi, *p_att_lo, *p_act_hi, *p_act_lo;
    __nv_bfloat16 *pq_hi, *pq_lo, *pk_hi, *pk_lo, *pv_hi, *pv_lo;
    __nv_bfloat16 *pWq_hi, *pWq_lo, *pWo_hi, *pWo_lo, *pWgu_hi, *pWgu_lo, *pWd_hi, *pWd_lo;
    cudaGetSymbolAddress((void**)&p_h,     g_h);
    cudaGetSymbolAddress((void**)&p_hn,    g_hn);
    cudaGetSymbolAddress((void**)&p_qkv,   g_qkv);
    cudaGetSymbolAddress((void**)&p_gu,    g_gu);
    cudaGetSymbolAddress((void**)&p_hn_hi, g_hn_hi);
    cudaGetSymbolAddress((void**)&p_hn_lo, g_hn_lo);
    cudaGetSymbolAddress((void**)&p_att_hi,g_att_hi);
    cudaGetSymbolAddress((void**)&p_att_lo,g_att_lo);
    cudaGetSymbolAddress((void**)&p_act_hi,g_act_hi);
    cudaGetSymbolAddress((void**)&p_act_lo,g_act_lo);
    cudaGetSymbolAddress((void**)&pq_hi,   g_qr_hi);
    cudaGetSymbolAddress((void**)&pq_lo,   g_qr_lo);
    cudaGetSymbolAddress((void**)&pk_hi,   g_kr_hi);
    cudaGetSymbolAddress((void**)&pk_lo,   g_kr_lo);
    cudaGetSymbolAddress((void**)&pv_hi,   g_vt_hi);
    cudaGetSymbolAddress((void**)&pv_lo,   g_vt_lo);
    cudaGetSymbolAddress((void**)&pWq_hi,  g_Wq_hi);
    cudaGetSymbolAddress((void**)&pWq_lo,  g_Wq_lo);
    cudaGetSymbolAddress((void**)&pWo_hi,  g_Wo_hi);
    cudaGetSymbolAddress((void**)&pWo_lo,  g_Wo_lo);
    cudaGetSymbolAddress((void**)&pWgu_hi, g_Wgu_hi);
    cudaGetSymbolAddress((void**)&pWgu_lo, g_Wgu_lo);
    cudaGetSymbolAddress((void**)&pWd_hi,  g_Wd_hi);
    cudaGetSymbolAddress((void**)&pWd_lo,  g_Wd_lo);

    cudaFuncSetAttribute(gemm_bf16x3, cudaFuncAttributeMaxDynamicSharedMemorySize, GSMEM_BYTES);
    cudaFuncSetAttribute(attn_mma,    cudaFuncAttributeMaxDynamicSharedMemorySize, ATT_SMEM);

    // ---- fold LoRA + transpose + bf16-split effective weights ----
    fold_kernel<<<dim3(32, 32, 24), 256>>>(Wqkv, Aqkv, Bqkv, pWq_hi,  pWq_lo,  H_, H_);
    fold_kernel<<<dim3(32, 32,  8), 256>>>(Wo,   Ao,   Bo,   pWo_hi,  pWo_lo,  H_, H_);
    fold_kernel<<<dim3(32, 88, 16), 256>>>(Wgu,  Agu,  Bgu,  pWgu_hi, pWgu_lo, H_, F_);
    fold_kernel<<<dim3(88, 32,  8), 256>>>(Wd,   Ad,   Bd,   pWd_hi,  pWd_lo,  F_, H_);

    // ---- embed + first rms ----
    init_h_kernel<<<dim3(4, M_), 256>>>(x, state_W, state_b);
    rms_kernel<<<M_, 256>>>(p_h, ln1, p_hn, p_hn_hi, p_hn_lo);

    // ---- layers ----
    for (int l = 0; l < L_; l++) {
        gemm_bf16x3<<<dim3(8, 16, 3), 128, GSMEM_BYTES>>>(
            p_hn_hi, p_hn_lo, pWq_hi + (size_t)l*3*HH_, pWq_lo + (size_t)l*3*HH_,
            p_qkv, H_, H_, H_, HH_, MH_, 0);
        qkv_prep<<<dim3(16, 16, 2), 256>>>(p_qkv, pq_hi, pq_lo, pk_hi, pk_lo, pv_hi, pv_lo);
        attn_mma<<<dim3(16, 32), 128, ATT_SMEM>>>(pq_hi, pq_lo, pk_hi, pk_lo, pv_hi, pv_lo,
                                                  p_att_hi, p_att_lo);
        gemm_bf16x3<<<dim3(8, 16, 2), 128, GSMEM_BYTES>>>(
            p_att_hi, p_att_lo, pWo_hi + (size_t)l*HH_, pWo_lo + (size_t)l*HH_,
            p_qkv, H_, 512, H_, 0, MH_, 512);
        rms3_kernel<<<M_, 256>>>(p_h, p_qkv, p_qkv + MH_, ln2 + (size_t)l*H_,
                                 p_hn, p_hn_hi, p_hn_lo);
        gemm_bf16x3<<<dim3(22, 16, 2), 128, GSMEM_BYTES>>>(
            p_hn_hi, p_hn_lo, pWgu_hi + (size_t)l*2*HF_, pWgu_lo + (size_t)l*2*HF_,
            p_gu, F_, H_, H_, HF_, MF_, 0);
        silu_kernel<<<(int)((MF_ + 255)/256), 256>>>(p_gu, p_gu + MF_, p_act_hi, p_act_lo, (int)MF_);
        gemm_bf16x3<<<dim3(8, 16, 2), 128, GSMEM_BYTES>>>(
            p_act_hi, p_act_lo, pWd_hi + (size_t)l*HF_, pWd_lo + (size_t)l*HF_,
            p_gu, H_, 1408, F_, 0, MH_, 1408);
        const float* wnext = (l < L_-1) ? (ln1 + (size_t)(l+1)*H_) : ln_f;
        rms3_kernel<<<M_, 256>>>(p_h, p_gu, p_gu + MH_, wnext,
                                 p_hn, p_hn_hi, p_hn_lo);
    }

    // ---- head + softmax ----
    head_kernel<<<M_, 256>>>(p_hn, head_W, head_b, temp, out);
}